// round 7
// baseline (speedup 1.0000x reference)
#include <cuda_runtime.h>
#include <cuda_bf16.h>
#include <math.h>
#include <stdint.h>

#define L_DIM   1024
#define S_DIM   64
#define H_DIM   768
#define AH      384
#define NH      6
#define HD      64
#define M_TOK   65536
#define MAX_DIST 20.0f
#define ROWB    80          // padded smem row bytes (32 bf16 + 16B pad) -> conflict-free ldmatrix

// ---------------- scratch (device globals; no allocs allowed) ----------------
__device__ __align__(16) __nv_bfloat16 g_hidb[M_TOK * H_DIM];
__device__ __align__(16) __nv_bfloat16 g_srcb[M_TOK * H_DIM];
__device__ __align__(16) __nv_bfloat16 g_qb[M_TOK * AH];
__device__ __align__(16) __nv_bfloat16 g_kb[M_TOK * AH];
__device__ __align__(16) __nv_bfloat16 g_vb[M_TOK * AH];
__device__ __align__(16) __nv_bfloat16 g_ctxb[M_TOK * AH];
__device__ __align__(16) __nv_bfloat16 g_Wqb[AH * H_DIM];
__device__ __align__(16) __nv_bfloat16 g_Wkb[AH * H_DIM];
__device__ __align__(16) __nv_bfloat16 g_Wvb[AH * H_DIM];
__device__ __align__(16) __nv_bfloat16 g_Wob[H_DIM * AH];
__device__ __align__(16) float g_bias[S_DIM * S_DIM];

// ---------------- asm helpers ----------------
#define CPA(dst, src) asm volatile("cp.async.cg.shared.global [%0], [%1], 16;" :: "r"(dst), "l"(src))
#define CP_COMMIT()   asm volatile("cp.async.commit_group;")
#define CP_WAIT(n)    asm volatile("cp.async.wait_group %0;" :: "n"(n))

__device__ __forceinline__ void ldm_x4(unsigned& r0, unsigned& r1, unsigned& r2, unsigned& r3,
                                       unsigned addr) {
    asm volatile("ldmatrix.sync.aligned.m8n8.x4.shared.b16 {%0,%1,%2,%3}, [%4];"
                 : "=r"(r0), "=r"(r1), "=r"(r2), "=r"(r3) : "r"(addr));
}
__device__ __forceinline__ void ldm_x4t(unsigned& r0, unsigned& r1, unsigned& r2, unsigned& r3,
                                        unsigned addr) {
    asm volatile("ldmatrix.sync.aligned.m8n8.x4.trans.shared.b16 {%0,%1,%2,%3}, [%4];"
                 : "=r"(r0), "=r"(r1), "=r"(r2), "=r"(r3) : "r"(addr));
}

__device__ __forceinline__ void mma_bf16(float* c, const unsigned* a, const unsigned* b) {
    asm volatile(
        "mma.sync.aligned.m16n8k16.row.col.f32.bf16.bf16.f32 "
        "{%0,%1,%2,%3},{%4,%5,%6,%7},{%8,%9},{%0,%1,%2,%3};"
        : "+f"(c[0]), "+f"(c[1]), "+f"(c[2]), "+f"(c[3])
        : "r"(a[0]), "r"(a[1]), "r"(a[2]), "r"(a[3]), "r"(b[0]), "r"(b[1]));
}

__device__ __forceinline__ unsigned pack_bf(float a, float b) {
    __nv_bfloat162 t = __floats2bfloat162_rn(a, b);
    return *reinterpret_cast<unsigned*>(&t);
}

// ---------------- fp32 -> bf16 conversion passes ----------------
__global__ void __launch_bounds__(256) cvt_act(const float4* __restrict__ hid,
                                               const float4* __restrict__ src) {
    const int n = M_TOK * H_DIM / 4;
    uint2* oh = reinterpret_cast<uint2*>(g_hidb);
    uint2* os = reinterpret_cast<uint2*>(g_srcb);
    for (int i = blockIdx.x * blockDim.x + threadIdx.x; i < n; i += gridDim.x * blockDim.x) {
        float4 h = hid[i];
        oh[i] = make_uint2(pack_bf(h.x, h.y), pack_bf(h.z, h.w));
        float4 s = src[i];
        os[i] = make_uint2(pack_bf(s.x, s.y), pack_bf(s.z, s.w));
    }
}

__global__ void __launch_bounds__(256) cvt_w(const float4* __restrict__ wq,
                                             const float4* __restrict__ wk,
                                             const float4* __restrict__ wv,
                                             const float4* __restrict__ wo) {
    const int per = AH * H_DIM / 4;
    const int a = blockIdx.y;
    const float4* src = (a == 0) ? wq : (a == 1) ? wk : (a == 2) ? wv : wo;
    uint2* dst = (a == 0) ? (uint2*)g_Wqb : (a == 1) ? (uint2*)g_Wkb
               : (a == 2) ? (uint2*)g_Wvb : (uint2*)g_Wob;
    for (int i = blockIdx.x * blockDim.x + threadIdx.x; i < per; i += gridDim.x * blockDim.x) {
        float4 v = src[i];
        dst[i] = make_uint2(pack_bf(v.x, v.y), pack_bf(v.z, v.w));
    }
}

// ---------------- FIRE bias + attention mask ----------------
__global__ void bias_kernel(const float* __restrict__ phylo, const float* __restrict__ am,
                            const float* __restrict__ cPtr, const float* __restrict__ w1,
                            const float* __restrict__ w2) {
    float c = fmaxf(cPtr[0], 0.f);
    float denom = logf(c * MAX_DIST + 1.f);
    for (int idx = threadIdx.x; idx < S_DIM * S_DIM; idx += blockDim.x) {
        int k = idx & 63;
        float r = logf(c * phylo[idx] + 1.f) / denom;
        float b = 0.f;
#pragma unroll
        for (int f = 0; f < 32; ++f) {
            float t = r * w1[f];
            float h = t / (1.f + __expf(-t));
            b += h * w2[f];
        }
        g_bias[idx] = b + am[k];
    }
}

// ---------------- bf16 tensor-core GEMM (CTA tile 256x128, 5-stage cp.async ring) ----------
// C[M,N] = A[M,K] @ W[N,K]^T (+bias)(+resid). BK=32. 256 threads: 8 warps 4m x 2n,
// warp tile 64x64 (acc 128 regs). fp32 accum, fragments via ldmatrix.
template <int KD, int NBLK, int NSEL, bool RES, bool OBF>
__global__ void __launch_bounds__(256) gemm_bf16(
    const __nv_bfloat16* __restrict__ A0, const __nv_bfloat16* __restrict__ A12,
    const __nv_bfloat16* __restrict__ W0, const float* __restrict__ bias0, void* __restrict__ out0,
    const __nv_bfloat16* __restrict__ W1, const float* __restrict__ bias1, void* __restrict__ out1,
    const __nv_bfloat16* __restrict__ W2, const float* __restrict__ bias2, void* __restrict__ out2,
    const float* __restrict__ resid)
{
    constexpr int LDO = NBLK * 128;
    constexpr int STG_A = 256 * ROWB;          // 20480
    constexpr int STG_B = 128 * ROWB;          // 10240
    constexpr int SLOT = STG_A + STG_B;        // 30720
    constexpr int NSTG = 5;
    extern __shared__ __align__(16) char smem[];   // NSTG * SLOT

    const int tid = threadIdx.x;
    const int sel = (NSEL > 1) ? (blockIdx.x / NBLK) : 0;
    const int n0 = (NSEL > 1 ? (blockIdx.x % NBLK) : blockIdx.x) * 128;
    const int m0 = blockIdx.y * 256;
    const __nv_bfloat16* A = (sel == 0) ? A0 : A12;
    const __nv_bfloat16* W = (sel == 0) ? W0 : (sel == 1) ? W1 : W2;
    const float* bias = (sel == 0) ? bias0 : (sel == 1) ? bias1 : bias2;
    void* out = (sel == 0) ? out0 : (sel == 1) ? out1 : out2;

    // producer mapping: lr = row group (0..63), lc = 16B chunk (0..3)
    const int lc = tid & 3;
    const int lr = tid >> 2;
    const __nv_bfloat16* Ag = A + (size_t)(m0 + lr) * KD + lc * 8;
    const __nv_bfloat16* Wg = W + (size_t)(n0 + lr) * KD + lc * 8;
    const unsigned smBase = (unsigned)__cvta_generic_to_shared(smem);
    const unsigned dBase = smBase + lr * ROWB + lc * 16;

    const int lane = tid & 31, warp = tid >> 5;
    const int wm = (warp & 3) * 64;
    const int wn = (warp >> 2) * 64;

    const unsigned aOff = (unsigned)((wm + (lane & 15)) * ROWB + (lane >> 4) * 16);
    const unsigned bOff = (unsigned)((wn + (lane & 7) + ((lane >> 4) & 1) * 8) * ROWB
                                     + ((lane >> 3) & 1) * 16);

    float acc[4][8][4];
#pragma unroll
    for (int a = 0; a < 4; ++a)
#pragma unroll
        for (int b = 0; b < 8; ++b)
#pragma unroll
            for (int c = 0; c < 4; ++c) acc[a][b][c] = 0.f;

    constexpr int NK = KD / 32;

#define FILL(slot, kt)                                                           \
    {                                                                            \
        const unsigned d = dBase + (unsigned)(slot) * SLOT;                      \
        const __nv_bfloat16* ap = Ag + (size_t)(kt) * 32;                        \
        const __nv_bfloat16* wp = Wg + (size_t)(kt) * 32;                        \
        CPA(d, ap);                                                              \
        CPA(d + 64 * ROWB, ap + (size_t)64 * KD);                                \
        CPA(d + 128 * ROWB, ap + (size_t)128 * KD);                              \
        CPA(d + 192 * ROWB, ap + (size_t)192 * KD);                              \
        CPA(d + STG_A, wp);                                                      \
        CPA(d + STG_A + 64 * ROWB, wp + (size_t)64 * KD);                        \
    }

    // prologue: stages 0..NSTG-2
#pragma unroll
    for (int i = 0; i < NSTG - 1; ++i) {
        FILL(i, i);
        CP_COMMIT();
    }

    int cur = 0, nxt = NSTG - 1;
    for (int kt = 0; kt < NK; ++kt) {
        CP_WAIT(NSTG - 2);
        __syncthreads();

        if (kt + NSTG - 1 < NK) FILL(nxt, kt + NSTG - 1);
        CP_COMMIT();

        const unsigned aBase = smBase + (unsigned)cur * SLOT;
        const unsigned bBase = aBase + STG_A;

#pragma unroll
        for (int ks = 0; ks < 2; ++ks) {
            unsigned afr[4][4];
#pragma unroll
            for (int mt = 0; mt < 4; ++mt)
                ldm_x4(afr[mt][0], afr[mt][1], afr[mt][2], afr[mt][3],
                       aBase + aOff + mt * 16 * ROWB + ks * 32);
            unsigned bfr[8][2];
#pragma unroll
            for (int np = 0; np < 4; ++np) {
                unsigned b0, b1, b2, b3;
                ldm_x4(b0, b1, b2, b3, bBase + bOff + np * 16 * ROWB + ks * 32);
                bfr[2 * np][0] = b0;     bfr[2 * np][1] = b1;
                bfr[2 * np + 1][0] = b2; bfr[2 * np + 1][1] = b3;
            }
#pragma unroll
            for (int mt = 0; mt < 4; ++mt)
#pragma unroll
                for (int nt = 0; nt < 8; ++nt)
                    mma_bf16(acc[mt][nt], afr[mt], bfr[nt]);
        }

        if (++cur == NSTG) cur = 0;
        if (++nxt == NSTG) nxt = 0;
    }

    // epilogue
    const int cRow = lane >> 2;
    const int cCol = (lane & 3) * 2;
#pragma unroll
    for (int mt = 0; mt < 4; ++mt) {
#pragma unroll
        for (int nt = 0; nt < 8; ++nt) {
            const int col = n0 + wn + nt * 8 + cCol;
            const float b0v = bias[col];
            const float b1v = bias[col + 1];
#pragma unroll
            for (int half = 0; half < 2; ++half) {
                const int row = m0 + wm + mt * 16 + cRow + half * 8;
                float vx = acc[mt][nt][half * 2 + 0] + b0v;
                float vy = acc[mt][nt][half * 2 + 1] + b1v;
                if (RES) {
                    const float2 r = *(const float2*)(resid + (size_t)row * LDO + col);
                    vx += r.x; vy += r.y;
                }
                if (OBF) {
                    *(unsigned*)((__nv_bfloat16*)out + (size_t)row * LDO + col) = pack_bf(vx, vy);
                } else {
                    float2 v; v.x = vx; v.y = vy;
                    *(float2*)((float*)out + (size_t)row * LDO + col) = v;
                }
            }
        }
    }
#undef FILL
}

// ---------------- tensor-core attention: one CTA per (l, h), 128 threads ----------------
__global__ void __launch_bounds__(128) attn_kernel() {
    __shared__ __align__(16) __nv_bfloat16 qs[64 * 72];
    __shared__ __align__(16) __nv_bfloat16 ks_[64 * 72];
    __shared__ __align__(16) __nv_bfloat16 vs[64 * 72];
    __shared__ __align__(16) float bs[64 * 68];

    const int l = blockIdx.x, h = blockIdx.y;
    const int tid = threadIdx.x;
    const int lane = tid & 31, w = tid >> 5;
    const size_t base = (size_t)l * 64 * AH + (size_t)h * HD;

    {
        const int r = tid >> 3, c8 = (tid & 7) * 8;
#pragma unroll
        for (int it = 0; it < 4; ++it) {
            const int s = it * 16 + r;
            const size_t g = base + (size_t)s * AH + c8;
            *(uint4*)&qs[s * 72 + c8] = *(const uint4*)(g_qb + g);
            *(uint4*)&ks_[s * 72 + c8] = *(const uint4*)(g_kb + g);
            *(uint4*)&vs[s * 72 + c8] = *(const uint4*)(g_vb + g);
        }
    }
#pragma unroll
    for (int i = 0; i < 8; ++i) {
        const int idx = i * 128 + tid;
        const int r = idx >> 4, c = (idx & 15) * 4;
        *(float4*)&bs[r * 68 + c] = *(const float4*)(g_bias + r * 64 + c);
    }
    __syncthreads();

    const unsigned qB = (unsigned)__cvta_generic_to_shared(qs);
    const unsigned kB = (unsigned)__cvta_generic_to_shared(ks_);
    const unsigned vB = (unsigned)__cvta_generic_to_shared(vs);

    float sc[8][4];
#pragma unroll
    for (int i = 0; i < 8; ++i)
#pragma unroll
        for (int j = 0; j < 4; ++j) sc[i][j] = 0.f;

    const unsigned aAddr = qB + (unsigned)((w * 16 + (lane & 15)) * 144 + (lane >> 4) * 16);
    const unsigned bRow = (lane & 7) + ((lane >> 4) & 1) * 8;
    const unsigned bColB = ((lane >> 3) & 1) * 16;

#pragma unroll
    for (int ksx = 0; ksx < 4; ++ksx) {
        unsigned a[4];
        ldm_x4(a[0], a[1], a[2], a[3], aAddr + ksx * 32);
#pragma unroll
        for (int np = 0; np < 4; ++np) {
            unsigned b[4];
            ldm_x4(b[0], b[1], b[2], b[3],
                   kB + (unsigned)((np * 16 + bRow) * 144) + ksx * 32 + bColB);
            mma_bf16(sc[2 * np], a, b);
            mma_bf16(sc[2 * np + 1], a, b + 2);
        }
    }

    const int rLo = w * 16 + (lane >> 2);
    const int cQ = 2 * (lane & 3);
    float mLo = -1e30f, mHi = -1e30f;
#pragma unroll
    for (int nt = 0; nt < 8; ++nt) {
        const int cb = nt * 8 + cQ;
        sc[nt][0] = sc[nt][0] * 0.125f + bs[rLo * 68 + cb];
        sc[nt][1] = sc[nt][1] * 0.125f + bs[rLo * 68 + cb + 1];
        sc[nt][2] = sc[nt][2] * 0.125f + bs[(rLo + 8) * 68 + cb];
        sc[nt][3] = sc[nt][3] * 0.125f + bs[(rLo + 8) * 68 + cb + 1];
        mLo = fmaxf(mLo, fmaxf(sc[nt][0], sc[nt][1]));
        mHi = fmaxf(mHi, fmaxf(sc[nt][2], sc[nt][3]));
    }
#pragma unroll
    for (int o = 1; o <= 2; o <<= 1) {
        mLo = fmaxf(mLo, __shfl_xor_sync(0xffffffffu, mLo, o));
        mHi = fmaxf(mHi, __shfl_xor_sync(0xffffffffu, mHi, o));
    }
    float sLo = 0.f, sHi = 0.f;
#pragma unroll
    for (int nt = 0; nt < 8; ++nt) {
        sc[nt][0] = __expf(sc[nt][0] - mLo); sLo += sc[nt][0];
        sc[nt][1] = __expf(sc[nt][1] - mLo); sLo += sc[nt][1];
        sc[nt][2] = __expf(sc[nt][2] - mHi); sHi += sc[nt][2];
        sc[nt][3] = __expf(sc[nt][3] - mHi); sHi += sc[nt][3];
    }
#pragma unroll
    for (int o = 1; o <= 2; o <<= 1) {
        sLo += __shfl_xor_sync(0xffffffffu, sLo, o);
        sHi += __shfl_xor_sync(0xffffffffu, sHi, o);
    }
    const float iLo = 1.f / sLo, iHi = 1.f / sHi;
#pragma unroll
    for (int nt = 0; nt < 8; ++nt) {
        sc[nt][0] *= iLo; sc[nt][1] *= iLo;
        sc[nt][2] *= iHi; sc[nt][3] *= iHi;
    }

    float o[8][4];
#pragma unroll
    for (int i = 0; i < 8; ++i)
#pragma unroll
        for (int j = 0; j < 4; ++j) o[i][j] = 0.f;

    const unsigned vRow = (lane & 7) + ((lane >> 3) & 1) * 8;
    const unsigned vColB = ((lane >> 4) & 1) * 16;

#pragma unroll
    for (int kk = 0; kk < 4; ++kk) {
        unsigned ap[4];
        ap[0] = pack_bf(sc[2 * kk][0], sc[2 * kk][1]);
        ap[1] = pack_bf(sc[2 * kk][2], sc[2 * kk][3]);
        ap[2] = pack_bf(sc[2 * kk + 1][0], sc[2 * kk + 1][1]);
        ap[3] = pack_bf(sc[2 * kk + 1][2], sc[2 * kk + 1][3]);
#pragma unroll
        for (int dp = 0; dp < 4; ++dp) {
            unsigned b[4];
            ldm_x4t(b[0], b[1], b[2], b[3],
                    vB + (unsigned)((kk * 16 + vRow) * 144) + dp * 32 + vColB);
            mma_bf16(o[2 * dp], ap, b);
            mma_bf16(o[2 * dp + 1], ap, b + 2);
        }
    }

#pragma unroll
    for (int nt = 0; nt < 8; ++nt) {
        const int col = nt * 8 + cQ;
        *(unsigned*)(g_ctxb + base + (size_t)rLo * AH + col) = pack_bf(o[nt][0], o[nt][1]);
        *(unsigned*)(g_ctxb + base + (size_t)(rLo + 8) * AH + col) = pack_bf(o[nt][2], o[nt][3]);
    }
}

// ---------------- LayerNorm (in place on d_out rows of 768) ----------------
__global__ void __launch_bounds__(256) ln_kernel(float* __restrict__ x,
                                                 const float* __restrict__ g,
                                                 const float* __restrict__ b) {
    const size_t row = blockIdx.x;
    float* p = x + row * H_DIM;
    const int tid = threadIdx.x;

    float v0 = p[tid], v1 = p[tid + 256], v2 = p[tid + 512];
    float s = v0 + v1 + v2;
    float q = v0 * v0 + v1 * v1 + v2 * v2;
#pragma unroll
    for (int o = 16; o; o >>= 1) {
        s += __shfl_xor_sync(0xffffffffu, s, o);
        q += __shfl_xor_sync(0xffffffffu, q, o);
    }
    __shared__ float ss[8], qs[8];
    __shared__ float mu_s, rs_s;
    if ((tid & 31) == 0) { ss[tid >> 5] = s; qs[tid >> 5] = q; }
    __syncthreads();
    if (tid == 0) {
        float S = 0.f, Q = 0.f;
#pragma unroll
        for (int i = 0; i < 8; ++i) { S += ss[i]; Q += qs[i]; }
        const float mu = S * (1.f / 768.f);
        const float var = Q * (1.f / 768.f) - mu * mu;
        mu_s = mu;
        rs_s = rsqrtf(var + 1e-12f);
    }
    __syncthreads();
    const float mu = mu_s, rs = rs_s;
    p[tid]       = (v0 - mu) * rs * g[tid]       + b[tid];
    p[tid + 256] = (v1 - mu) * rs * g[tid + 256] + b[tid + 256];
    p[tid + 512] = (v2 - mu) * rs * g[tid + 512] + b[tid + 512];
}

// ---------------- launch ----------------
extern "C" void kernel_launch(void* const* d_in, const int* in_sizes, int n_in,
                              void* d_out, int out_size) {
    const float* hidden = (const float*)d_in[0];
    const float* source = (const float*)d_in[1];
    const float* amask  = (const float*)d_in[2];
    const float* phylo  = (const float*)d_in[3];
    const float* cP     = (const float*)d_in[4];
    const float* w1     = (const float*)d_in[5];
    const float* w2     = (const float*)d_in[6];
    const float* Wq     = (const float*)d_in[7];
    const float* bq     = (const float*)d_in[8];
    const float* Wk     = (const float*)d_in[9];
    const float* bk     = (const float*)d_in[10];
    const float* Wv     = (const float*)d_in[11];
    const float* bv     = (const float*)d_in[12];
    const float* Wo     = (const float*)d_in[13];
    const float* bo     = (const float*)d_in[14];
    const float* lng    = (const float*)d_in[15];
    const float* lnb    = (const float*)d_in[16];
    float* out = (float*)d_out;

    void *hb, *sb, *cb, *qa, *ka, *va, *wqb, *wkb, *wvb, *wob;
    cudaGetSymbolAddress(&hb, g_hidb);
    cudaGetSymbolAddress(&sb, g_srcb);
    cudaGetSymbolAddress(&cb, g_ctxb);
    cudaGetSymbolAddress(&qa, g_qb);
    cudaGetSymbolAddress(&ka, g_kb);
    cudaGetSymbolAddress(&va, g_vb);
    cudaGetSymbolAddress(&wqb, g_Wqb);
    cudaGetSymbolAddress(&wkb, g_Wkb);
    cudaGetSymbolAddress(&wvb, g_Wvb);
    cudaGetSymbolAddress(&wob, g_Wob);

    const int SMEM_GEMM = 5 * (256 + 128) * ROWB;   // 153600
    cudaFuncSetAttribute(gemm_bf16<768, 3, 3, false, true>,
                         cudaFuncAttributeMaxDynamicSharedMemorySize, SMEM_GEMM);
    cudaFuncSetAttribute(gemm_bf16<384, 6, 1, true, false>,
                         cudaFuncAttributeMaxDynamicSharedMemorySize, SMEM_GEMM);

    cvt_act<<<2048, 256>>>((const float4*)hidden, (const float4*)source);
    cvt_w<<<dim3(288, 4), 256>>>((const float4*)Wq, (const float4*)Wk,
                                 (const float4*)Wv, (const float4*)Wo);
    bias_kernel<<<1, 256>>>(phylo, amask, cP, w1, w2);

    // fused Q + K + V projections -> bf16 (sel 0: hidden@Wq, sel 1: source@Wk, sel 2: source@Wv)
    gemm_bf16<768, 3, 3, false, true><<<dim3(9, 256), 256, SMEM_GEMM>>>(
        (const __nv_bfloat16*)hb, (const __nv_bfloat16*)sb,
        (const __nv_bfloat16*)wqb, bq, qa,
        (const __nv_bfloat16*)wkb, bk, ka,
        (const __nv_bfloat16*)wvb, bv, va,
        nullptr);

    attn_kernel<<<dim3(L_DIM, NH), 128>>>();

    // Output projection + bias + residual -> fp32
    gemm_bf16<384, 6, 1, true, false><<<dim3(6, 256), 256, SMEM_GEMM>>>(
        (const __nv_bfloat16*)cb, nullptr,
        (const __nv_bfloat16*)wob, bo, out,
        nullptr, nullptr, nullptr,
        nullptr, nullptr, nullptr,
        hidden);

    ln_kernel<<<M_TOK, 256>>>(out, lng, lnb);
}

// round 11
// speedup vs baseline: 1.1550x; 1.1550x over previous
#include <cuda_runtime.h>
#include <cuda_bf16.h>
#include <math.h>
#include <stdint.h>

#define L_DIM   1024
#define S_DIM   64
#define H_DIM   768
#define AH      384
#define NH      6
#define HD      64
#define M_TOK   65536
#define MAX_DIST 20.0f
#define ROWB    80          // padded smem row bytes (32 bf16 + 16B pad) -> conflict-free ldmatrix

// ---------------- scratch (device globals; no allocs allowed) ----------------
__device__ __align__(16) __nv_bfloat16 g_hidb[M_TOK * H_DIM];
__device__ __align__(16) __nv_bfloat16 g_srcb[M_TOK * H_DIM];
__device__ __align__(16) __nv_bfloat16 g_qb[M_TOK * AH];
__device__ __align__(16) __nv_bfloat16 g_kb[M_TOK * AH];
__device__ __align__(16) __nv_bfloat16 g_vb[M_TOK * AH];
__device__ __align__(16) __nv_bfloat16 g_ctxb[M_TOK * AH];
__device__ __align__(16) __nv_bfloat16 g_Wqb[AH * H_DIM];
__device__ __align__(16) __nv_bfloat16 g_Wkb[AH * H_DIM];
__device__ __align__(16) __nv_bfloat16 g_Wvb[AH * H_DIM];
__device__ __align__(16) __nv_bfloat16 g_Wob[H_DIM * AH];
__device__ __align__(16) float g_bias[S_DIM * S_DIM];

// ---------------- asm helpers ----------------
#define CPA(dst, src) asm volatile("cp.async.cg.shared.global [%0], [%1], 16;" :: "r"(dst), "l"(src))
#define CP_COMMIT()   asm volatile("cp.async.commit_group;")
#define CP_WAIT(n)    asm volatile("cp.async.wait_group %0;" :: "n"(n))

__device__ __forceinline__ void ldm_x4(unsigned& r0, unsigned& r1, unsigned& r2, unsigned& r3,
                                       unsigned addr) {
    asm volatile("ldmatrix.sync.aligned.m8n8.x4.shared.b16 {%0,%1,%2,%3}, [%4];"
                 : "=r"(r0), "=r"(r1), "=r"(r2), "=r"(r3) : "r"(addr));
}
__device__ __forceinline__ void ldm_x4t(unsigned& r0, unsigned& r1, unsigned& r2, unsigned& r3,
                                        unsigned addr) {
    asm volatile("ldmatrix.sync.aligned.m8n8.x4.trans.shared.b16 {%0,%1,%2,%3}, [%4];"
                 : "=r"(r0), "=r"(r1), "=r"(r2), "=r"(r3) : "r"(addr));
}

__device__ __forceinline__ void mma_bf16(float* c, const unsigned* a, const unsigned* b) {
    asm volatile(
        "mma.sync.aligned.m16n8k16.row.col.f32.bf16.bf16.f32 "
        "{%0,%1,%2,%3},{%4,%5,%6,%7},{%8,%9},{%0,%1,%2,%3};"
        : "+f"(c[0]), "+f"(c[1]), "+f"(c[2]), "+f"(c[3])
        : "r"(a[0]), "r"(a[1]), "r"(a[2]), "r"(a[3]), "r"(b[0]), "r"(b[1]));
}

__device__ __forceinline__ unsigned pack_bf(float a, float b) {
    __nv_bfloat162 t = __floats2bfloat162_rn(a, b);
    return *reinterpret_cast<unsigned*>(&t);
}

// ---------------- fp32 -> bf16 conversion passes ----------------
__global__ void __launch_bounds__(256) cvt_act(const float4* __restrict__ hid,
                                               const float4* __restrict__ src) {
    const int n = M_TOK * H_DIM / 4;
    uint2* oh = reinterpret_cast<uint2*>(g_hidb);
    uint2* os = reinterpret_cast<uint2*>(g_srcb);
    for (int i = blockIdx.x * blockDim.x + threadIdx.x; i < n; i += gridDim.x * blockDim.x) {
        float4 h = hid[i];
        oh[i] = make_uint2(pack_bf(h.x, h.y), pack_bf(h.z, h.w));
        float4 s = src[i];
        os[i] = make_uint2(pack_bf(s.x, s.y), pack_bf(s.z, s.w));
    }
}

__global__ void __launch_bounds__(256) cvt_w(const float4* __restrict__ wq,
                                             const float4* __restrict__ wk,
                                             const float4* __restrict__ wv,
                                             const float4* __restrict__ wo) {
    const int per = AH * H_DIM / 4;
    const int a = blockIdx.y;
    const float4* src = (a == 0) ? wq : (a == 1) ? wk : (a == 2) ? wv : wo;
    uint2* dst = (a == 0) ? (uint2*)g_Wqb : (a == 1) ? (uint2*)g_Wkb
               : (a == 2) ? (uint2*)g_Wvb : (uint2*)g_Wob;
    for (int i = blockIdx.x * blockDim.x + threadIdx.x; i < per; i += gridDim.x * blockDim.x) {
        float4 v = src[i];
        dst[i] = make_uint2(pack_bf(v.x, v.y), pack_bf(v.z, v.w));
    }
}

// ---------------- FIRE bias + attention mask ----------------
__global__ void bias_kernel(const float* __restrict__ phylo, const float* __restrict__ am,
                            const float* __restrict__ cPtr, const float* __restrict__ w1,
                            const float* __restrict__ w2) {
    float c = fmaxf(cPtr[0], 0.f);
    float denom = logf(c * MAX_DIST + 1.f);
    for (int idx = threadIdx.x; idx < S_DIM * S_DIM; idx += blockDim.x) {
        int k = idx & 63;
        float r = logf(c * phylo[idx] + 1.f) / denom;
        float b = 0.f;
#pragma unroll
        for (int f = 0; f < 32; ++f) {
            float t = r * w1[f];
            float h = t / (1.f + __expf(-t));
            b += h * w2[f];
        }
        g_bias[idx] = b + am[k];
    }
}

// ---------------- bf16 tensor-core GEMM (CTA 128x128, 4 warps 2m x 2n, warp tile 64x64) ----
// C[M,N] = A[M,K] @ W[N,K]^T (+bias)(+resid). BK=32, 4-stage cp.async ring, 128 threads.
// Minimal crossbar traffic: A and B each re-read only 2x per kt.
template <int KD, int NBLK, int NSEL, bool RES, bool OBF>
__global__ void __launch_bounds__(128, 2) gemm_bf16(
    const __nv_bfloat16* __restrict__ A0, const __nv_bfloat16* __restrict__ A12,
    const __nv_bfloat16* __restrict__ W0, const float* __restrict__ bias0, void* __restrict__ out0,
    const __nv_bfloat16* __restrict__ W1, const float* __restrict__ bias1, void* __restrict__ out1,
    const __nv_bfloat16* __restrict__ W2, const float* __restrict__ bias2, void* __restrict__ out2,
    const float* __restrict__ resid)
{
    constexpr int LDO = NBLK * 128;
    constexpr int STG = 128 * ROWB;           // 10240 bytes per operand tile
    constexpr int NSTG = 4;
    extern __shared__ __align__(16) char smem[];   // NSTG * 2 * STG

    const int tid = threadIdx.x;
    const int sel = (NSEL > 1) ? (blockIdx.x / NBLK) : 0;
    const int n0 = (NSEL > 1 ? (blockIdx.x % NBLK) : blockIdx.x) * 128;
    const int m0 = blockIdx.y * 128;
    const __nv_bfloat16* A = (sel == 0) ? A0 : A12;
    const __nv_bfloat16* W = (sel == 0) ? W0 : (sel == 1) ? W1 : W2;
    const float* bias = (sel == 0) ? bias0 : (sel == 1) ? bias1 : bias2;
    void* out = (sel == 0) ? out0 : (sel == 1) ? out1 : out2;

    // producer: 128 threads, 4 rows each for A and for B (16B chunk lc of row lr+32i)
    const int lc = tid & 3;
    const int lr = tid >> 2;                  // 0..31
    const __nv_bfloat16* Ag = A + (size_t)(m0 + lr) * KD + lc * 8;
    const __nv_bfloat16* Wg = W + (size_t)(n0 + lr) * KD + lc * 8;
    const unsigned smBase = (unsigned)__cvta_generic_to_shared(smem);
    const unsigned dBase = smBase + lr * ROWB + lc * 16;

    const int lane = tid & 31, warp = tid >> 5;
    const int wm = (warp & 1) * 64;
    const int wn = (warp >> 1) * 64;

    // A fragment ldmatrix: row = wm + (lane&15) (+mt*16), 16B col = lane>>4 (+ks*2)
    const unsigned aOff = (unsigned)((wm + (lane & 15)) * ROWB + (lane >> 4) * 16);
    // B fragment ldmatrix (two 8-n tiles x two 8-k chunks per x4)
    const unsigned bOff = (unsigned)((wn + (lane & 7) + ((lane >> 4) & 1) * 8) * ROWB
                                     + ((lane >> 3) & 1) * 16);

    float acc[4][8][4];
#pragma unroll
    for (int a = 0; a < 4; ++a)
#pragma unroll
        for (int b = 0; b < 8; ++b)
#pragma unroll
            for (int c = 0; c < 4; ++c) acc[a][b][c] = 0.f;

    constexpr int NK = KD / 32;

#define FILL(slot, kt)                                                           \
    {                                                                            \
        const unsigned d = dBase + (unsigned)(slot) * 2 * STG;                   \
        const __nv_bfloat16* ap = Ag + (size_t)(kt) * 32;                        \
        const __nv_bfloat16* wp = Wg + (size_t)(kt) * 32;                        \
        CPA(d, ap);                                                              \
        CPA(d + 32 * ROWB, ap + (size_t)32 * KD);                                \
        CPA(d + 64 * ROWB, ap + (size_t)64 * KD);                                \
        CPA(d + 96 * ROWB, ap + (size_t)96 * KD);                                \
        CPA(d + STG, wp);                                                        \
        CPA(d + STG + 32 * ROWB, wp + (size_t)32 * KD);                          \
        CPA(d + STG + 64 * ROWB, wp + (size_t)64 * KD);                          \
        CPA(d + STG + 96 * ROWB, wp + (size_t)96 * KD);                          \
    }

    // prologue: stages 0..NSTG-2
#pragma unroll
    for (int i = 0; i < NSTG - 1; ++i) {
        FILL(i, i);
        CP_COMMIT();
    }

    for (int kt = 0; kt < NK; ++kt) {
        CP_WAIT(NSTG - 2);
        __syncthreads();

        const int nf = kt + NSTG - 1;
        if (nf < NK) FILL(nf & 3, nf);
        CP_COMMIT();

        const unsigned aBase = smBase + (kt & 3) * 2 * STG;
        const unsigned bBase = aBase + STG;

#pragma unroll
        for (int ks = 0; ks < 2; ++ks) {
            unsigned afr[4][4];
#pragma unroll
            for (int mt = 0; mt < 4; ++mt)
                ldm_x4(afr[mt][0], afr[mt][1], afr[mt][2], afr[mt][3],
                       aBase + aOff + mt * 16 * ROWB + ks * 32);
            unsigned bfr[8][2];
#pragma unroll
            for (int np = 0; np < 4; ++np) {
                unsigned b0, b1, b2, b3;
                ldm_x4(b0, b1, b2, b3, bBase + bOff + np * 16 * ROWB + ks * 32);
                bfr[2 * np][0] = b0;     bfr[2 * np][1] = b1;
                bfr[2 * np + 1][0] = b2; bfr[2 * np + 1][1] = b3;
            }
#pragma unroll
            for (int mt = 0; mt < 4; ++mt)
#pragma unroll
                for (int nt = 0; nt < 8; ++nt)
                    mma_bf16(acc[mt][nt], afr[mt], bfr[nt]);
        }
    }

    // epilogue
    const int cRow = lane >> 2;
    const int cCol = (lane & 3) * 2;
#pragma unroll
    for (int mt = 0; mt < 4; ++mt) {
#pragma unroll
        for (int nt = 0; nt < 8; ++nt) {
            const int col = n0 + wn + nt * 8 + cCol;
            const float b0v = bias[col];
            const float b1v = bias[col + 1];
#pragma unroll
            for (int half = 0; half < 2; ++half) {
                const int row = m0 + wm + mt * 16 + cRow + half * 8;
                float vx = acc[mt][nt][half * 2 + 0] + b0v;
                float vy = acc[mt][nt][half * 2 + 1] + b1v;
                if (RES) {
                    const float2 r = *(const float2*)(resid + (size_t)row * LDO + col);
                    vx += r.x; vy += r.y;
                }
                if (OBF) {
                    *(unsigned*)((__nv_bfloat16*)out + (size_t)row * LDO + col) = pack_bf(vx, vy);
                } else {
                    float2 v; v.x = vx; v.y = vy;
                    *(float2*)((float*)out + (size_t)row * LDO + col) = v;
                }
            }
        }
    }
#undef FILL
}

// ---------------- tensor-core attention: one CTA per (l, h), 128 threads ----------------
__global__ void __launch_bounds__(128) attn_kernel() {
    __shared__ __align__(16) __nv_bfloat16 qs[64 * 72];
    __shared__ __align__(16) __nv_bfloat16 ks_[64 * 72];
    __shared__ __align__(16) __nv_bfloat16 vs[64 * 72];
    __shared__ __align__(16) float bs[64 * 68];

    const int l = blockIdx.x, h = blockIdx.y;
    const int tid = threadIdx.x;
    const int lane = tid & 31, w = tid >> 5;
    const size_t base = (size_t)l * 64 * AH + (size_t)h * HD;

    {
        const int r = tid >> 3, c8 = (tid & 7) * 8;
#pragma unroll
        for (int it = 0; it < 4; ++it) {
            const int s = it * 16 + r;
            const size_t g = base + (size_t)s * AH + c8;
            *(uint4*)&qs[s * 72 + c8] = *(const uint4*)(g_qb + g);
            *(uint4*)&ks_[s * 72 + c8] = *(const uint4*)(g_kb + g);
            *(uint4*)&vs[s * 72 + c8] = *(const uint4*)(g_vb + g);
        }
    }
#pragma unroll
    for (int i = 0; i < 8; ++i) {
        const int idx = i * 128 + tid;
        const int r = idx >> 4, c = (idx & 15) * 4;
        *(float4*)&bs[r * 68 + c] = *(const float4*)(g_bias + r * 64 + c);
    }
    __syncthreads();

    const unsigned qB = (unsigned)__cvta_generic_to_shared(qs);
    const unsigned kB = (unsigned)__cvta_generic_to_shared(ks_);
    const unsigned vB = (unsigned)__cvta_generic_to_shared(vs);

    float sc[8][4];
#pragma unroll
    for (int i = 0; i < 8; ++i)
#pragma unroll
        for (int j = 0; j < 4; ++j) sc[i][j] = 0.f;

    const unsigned aAddr = qB + (unsigned)((w * 16 + (lane & 15)) * 144 + (lane >> 4) * 16);
    const unsigned bRow = (lane & 7) + ((lane >> 4) & 1) * 8;
    const unsigned bColB = ((lane >> 3) & 1) * 16;

#pragma unroll
    for (int ksx = 0; ksx < 4; ++ksx) {
        unsigned a[4];
        ldm_x4(a[0], a[1], a[2], a[3], aAddr + ksx * 32);
#pragma unroll
        for (int np = 0; np < 4; ++np) {
            unsigned b[4];
            ldm_x4(b[0], b[1], b[2], b[3],
                   kB + (unsigned)((np * 16 + bRow) * 144) + ksx * 32 + bColB);
            mma_bf16(sc[2 * np], a, b);
            mma_bf16(sc[2 * np + 1], a, b + 2);
        }
    }

    const int rLo = w * 16 + (lane >> 2);
    const int cQ = 2 * (lane & 3);
    float mLo = -1e30f, mHi = -1e30f;
#pragma unroll
    for (int nt = 0; nt < 8; ++nt) {
        const int cb = nt * 8 + cQ;
        sc[nt][0] = sc[nt][0] * 0.125f + bs[rLo * 68 + cb];
        sc[nt][1] = sc[nt][1] * 0.125f + bs[rLo * 68 + cb + 1];
        sc[nt][2] = sc[nt][2] * 0.125f + bs[(rLo + 8) * 68 + cb];
        sc[nt][3] = sc[nt][3] * 0.125f + bs[(rLo + 8) * 68 + cb + 1];
        mLo = fmaxf(mLo, fmaxf(sc[nt][0], sc[nt][1]));
        mHi = fmaxf(mHi, fmaxf(sc[nt][2], sc[nt][3]));
    }
#pragma unroll
    for (int o = 1; o <= 2; o <<= 1) {
        mLo = fmaxf(mLo, __shfl_xor_sync(0xffffffffu, mLo, o));
        mHi = fmaxf(mHi, __shfl_xor_sync(0xffffffffu, mHi, o));
    }
    float sLo = 0.f, sHi = 0.f;
#pragma unroll
    for (int nt = 0; nt < 8; ++nt) {
        sc[nt][0] = __expf(sc[nt][0] - mLo); sLo += sc[nt][0];
        sc[nt][1] = __expf(sc[nt][1] - mLo); sLo += sc[nt][1];
        sc[nt][2] = __expf(sc[nt][2] - mHi); sHi += sc[nt][2];
        sc[nt][3] = __expf(sc[nt][3] - mHi); sHi += sc[nt][3];
    }
#pragma unroll
    for (int o = 1; o <= 2; o <<= 1) {
        sLo += __shfl_xor_sync(0xffffffffu, sLo, o);
        sHi += __shfl_xor_sync(0xffffffffu, sHi, o);
    }
    const float iLo = 1.f / sLo, iHi = 1.f / sHi;
#pragma unroll
    for (int nt = 0; nt < 8; ++nt) {
        sc[nt][0] *= iLo; sc[nt][1] *= iLo;
        sc[nt][2] *= iHi; sc[nt][3] *= iHi;
    }

    float o[8][4];
#pragma unroll
    for (int i = 0; i < 8; ++i)
#pragma unroll
        for (int j = 0; j < 4; ++j) o[i][j] = 0.f;

    const unsigned vRow = (lane & 7) + ((lane >> 3) & 1) * 8;
    const unsigned vColB = ((lane >> 4) & 1) * 16;

#pragma unroll
    for (int kk = 0; kk < 4; ++kk) {
        unsigned ap[4];
        ap[0] = pack_bf(sc[2 * kk][0], sc[2 * kk][1]);
        ap[1] = pack_bf(sc[2 * kk][2], sc[2 * kk][3]);
        ap[2] = pack_bf(sc[2 * kk + 1][0], sc[2 * kk + 1][1]);
        ap[3] = pack_bf(sc[2 * kk + 1][2], sc[2 * kk + 1][3]);
#pragma unroll
        for (int dp = 0; dp < 4; ++dp) {
            unsigned b[4];
            ldm_x4t(b[0], b[1], b[2], b[3],
                    vB + (unsigned)((kk * 16 + vRow) * 144) + dp * 32 + vColB);
            mma_bf16(o[2 * dp], ap, b);
            mma_bf16(o[2 * dp + 1], ap, b + 2);
        }
    }

#pragma unroll
    for (int nt = 0; nt < 8; ++nt) {
        const int col = nt * 8 + cQ;
        *(unsigned*)(g_ctxb + base + (size_t)rLo * AH + col) = pack_bf(o[nt][0], o[nt][1]);
        *(unsigned*)(g_ctxb + base + (size_t)(rLo + 8) * AH + col) = pack_bf(o[nt][2], o[nt][3]);
    }
}

// ---------------- LayerNorm (in place on d_out rows of 768) ----------------
__global__ void __launch_bounds__(256) ln_kernel(float* __restrict__ x,
                                                 const float* __restrict__ g,
                                                 const float* __restrict__ b) {
    const size_t row = blockIdx.x;
    float* p = x + row * H_DIM;
    const int tid = threadIdx.x;

    float v0 = p[tid], v1 = p[tid + 256], v2 = p[tid + 512];
    float s = v0 + v1 + v2;
    float q = v0 * v0 + v1 * v1 + v2 * v2;
#pragma unroll
    for (int o = 16; o; o >>= 1) {
        s += __shfl_xor_sync(0xffffffffu, s, o);
        q += __shfl_xor_sync(0xffffffffu, q, o);
    }
    __shared__ float ss[8], qs[8];
    __shared__ float mu_s, rs_s;
    if ((tid & 31) == 0) { ss[tid >> 5] = s; qs[tid >> 5] = q; }
    __syncthreads();
    if (tid == 0) {
        float S = 0.f, Q = 0.f;
#pragma unroll
        for (int i = 0; i < 8; ++i) { S += ss[i]; Q += qs[i]; }
        const float mu = S * (1.f / 768.f);
        const float var = Q * (1.f / 768.f) - mu * mu;
        mu_s = mu;
        rs_s = rsqrtf(var + 1e-12f);
    }
    __syncthreads();
    const float mu = mu_s, rs = rs_s;
    p[tid]       = (v0 - mu) * rs * g[tid]       + b[tid];
    p[tid + 256] = (v1 - mu) * rs * g[tid + 256] + b[tid + 256];
    p[tid + 512] = (v2 - mu) * rs * g[tid + 512] + b[tid + 512];
}

// ---------------- launch ----------------
extern "C" void kernel_launch(void* const* d_in, const int* in_sizes, int n_in,
                              void* d_out, int out_size) {
    const float* hidden = (const float*)d_in[0];
    const float* source = (const float*)d_in[1];
    const float* amask  = (const float*)d_in[2];
    const float* phylo  = (const float*)d_in[3];
    const float* cP     = (const float*)d_in[4];
    const float* w1     = (const float*)d_in[5];
    const float* w2     = (const float*)d_in[6];
    const float* Wq     = (const float*)d_in[7];
    const float* bq     = (const float*)d_in[8];
    const float* Wk     = (const float*)d_in[9];
    const float* bk     = (const float*)d_in[10];
    const float* Wv     = (const float*)d_in[11];
    const float* bv     = (const float*)d_in[12];
    const float* Wo     = (const float*)d_in[13];
    const float* bo     = (const float*)d_in[14];
    const float* lng    = (const float*)d_in[15];
    const float* lnb    = (const float*)d_in[16];
    float* out = (float*)d_out;

    void *hb, *sb, *cb, *qa, *ka, *va, *wqb, *wkb, *wvb, *wob;
    cudaGetSymbolAddress(&hb, g_hidb);
    cudaGetSymbolAddress(&sb, g_srcb);
    cudaGetSymbolAddress(&cb, g_ctxb);
    cudaGetSymbolAddress(&qa, g_qb);
    cudaGetSymbolAddress(&ka, g_kb);
    cudaGetSymbolAddress(&va, g_vb);
    cudaGetSymbolAddress(&wqb, g_Wqb);
    cudaGetSymbolAddress(&wkb, g_Wkb);
    cudaGetSymbolAddress(&wvb, g_Wvb);
    cudaGetSymbolAddress(&wob, g_Wob);

    const int SMEM_GEMM = 4 * 2 * 128 * ROWB;   // 81920
    cudaFuncSetAttribute(gemm_bf16<768, 3, 3, false, true>,
                         cudaFuncAttributeMaxDynamicSharedMemorySize, SMEM_GEMM);
    cudaFuncSetAttribute(gemm_bf16<384, 6, 1, true, false>,
                         cudaFuncAttributeMaxDynamicSharedMemorySize, SMEM_GEMM);

    cvt_act<<<2048, 256>>>((const float4*)hidden, (const float4*)source);
    cvt_w<<<dim3(288, 4), 256>>>((const float4*)Wq, (const float4*)Wk,
                                 (const float4*)Wv, (const float4*)Wo);
    bias_kernel<<<1, 256>>>(phylo, amask, cP, w1, w2);

    // fused Q + K + V projections -> bf16 (sel 0: hidden@Wq, sel 1: source@Wk, sel 2: source@Wv)
    gemm_bf16<768, 3, 3, false, true><<<dim3(9, 512), 128, SMEM_GEMM>>>(
        (const __nv_bfloat16*)hb, (const __nv_bfloat16*)sb,
        (const __nv_bfloat16*)wqb, bq, qa,
        (const __nv_bfloat16*)wkb, bk, ka,
        (const __nv_bfloat16*)wvb, bv, va,
        nullptr);

    attn_kernel<<<dim3(L_DIM, NH), 128>>>();

    // Output projection + bias + residual -> fp32
    gemm_bf16<384, 6, 1, true, false><<<dim3(6, 512), 128, SMEM_GEMM>>>(
        (const __nv_bfloat16*)cb, nullptr,
        (const __nv_bfloat16*)wob, bo, out,
        nullptr, nullptr, nullptr,
        nullptr, nullptr, nullptr,
        hidden);

    ln_kernel<<<M_TOK, 256>>>(out, lng, lnb);
}

// round 14
// speedup vs baseline: 1.2253x; 1.0609x over previous
#include <cuda_runtime.h>
#include <cuda_bf16.h>
#include <math.h>
#include <stdint.h>

#define L_DIM   1024
#define S_DIM   64
#define H_DIM   768
#define AH      384
#define NH      6
#define HD      64
#define M_TOK   65536
#define MAX_DIST 20.0f
#define ROWB    80          // padded smem row bytes (32 bf16 + 16B pad) -> conflict-free ldmatrix

// ---------------- scratch (device globals; no allocs allowed) ----------------
__device__ __align__(16) __nv_bfloat16 g_qb[M_TOK * AH];
__device__ __align__(16) __nv_bfloat16 g_kb[M_TOK * AH];
__device__ __align__(16) __nv_bfloat16 g_vb[M_TOK * AH];
__device__ __align__(16) __nv_bfloat16 g_ctxb[M_TOK * AH];
__device__ __align__(16) __nv_bfloat16 g_Wqb[AH * H_DIM];
__device__ __align__(16) __nv_bfloat16 g_Wkb[AH * H_DIM];
__device__ __align__(16) __nv_bfloat16 g_Wvb[AH * H_DIM];
__device__ __align__(16) __nv_bfloat16 g_Wob[H_DIM * AH];
__device__ __align__(16) float g_bias[S_DIM * S_DIM];

// ---------------- asm helpers ----------------
#define CPA(dst, src) asm volatile("cp.async.cg.shared.global [%0], [%1], 16;" :: "r"(dst), "l"(src))
#define CP_COMMIT()   asm volatile("cp.async.commit_group;")
#define CP_WAIT(n)    asm volatile("cp.async.wait_group %0;" :: "n"(n))

__device__ __forceinline__ void ldm_x4(unsigned& r0, unsigned& r1, unsigned& r2, unsigned& r3,
                                       unsigned addr) {
    asm volatile("ldmatrix.sync.aligned.m8n8.x4.shared.b16 {%0,%1,%2,%3}, [%4];"
                 : "=r"(r0), "=r"(r1), "=r"(r2), "=r"(r3) : "r"(addr));
}
__device__ __forceinline__ void ldm_x4t(unsigned& r0, unsigned& r1, unsigned& r2, unsigned& r3,
                                        unsigned addr) {
    asm volatile("ldmatrix.sync.aligned.m8n8.x4.trans.shared.b16 {%0,%1,%2,%3}, [%4];"
                 : "=r"(r0), "=r"(r1), "=r"(r2), "=r"(r3) : "r"(addr));
}

__device__ __forceinline__ void mma_bf16(float* c, const unsigned* a, const unsigned* b) {
    asm volatile(
        "mma.sync.aligned.m16n8k16.row.col.f32.bf16.bf16.f32 "
        "{%0,%1,%2,%3},{%4,%5,%6,%7},{%8,%9},{%0,%1,%2,%3};"
        : "+f"(c[0]), "+f"(c[1]), "+f"(c[2]), "+f"(c[3])
        : "r"(a[0]), "r"(a[1]), "r"(a[2]), "r"(a[3]), "r"(b[0]), "r"(b[1]));
}

__device__ __forceinline__ unsigned pack_bf(float a, float b) {
    __nv_bfloat162 t = __floats2bfloat162_rn(a, b);
    return *reinterpret_cast<unsigned*>(&t);
}

// ---------------- weights fp32 -> bf16 ----------------
__global__ void __launch_bounds__(256) cvt_w(const float4* __restrict__ wq,
                                             const float4* __restrict__ wk,
                                             const float4* __restrict__ wv,
                                             const float4* __restrict__ wo) {
    const int per = AH * H_DIM / 4;
    const int a = blockIdx.y;
    const float4* src = (a == 0) ? wq : (a == 1) ? wk : (a == 2) ? wv : wo;
    uint2* dst = (a == 0) ? (uint2*)g_Wqb : (a == 1) ? (uint2*)g_Wkb
               : (a == 2) ? (uint2*)g_Wvb : (uint2*)g_Wob;
    for (int i = blockIdx.x * blockDim.x + threadIdx.x; i < per; i += gridDim.x * blockDim.x) {
        float4 v = src[i];
        dst[i] = make_uint2(pack_bf(v.x, v.y), pack_bf(v.z, v.w));
    }
}

// ---------------- FIRE bias + attention mask ----------------
__global__ void bias_kernel(const float* __restrict__ phylo, const float* __restrict__ am,
                            const float* __restrict__ cPtr, const float* __restrict__ w1,
                            const float* __restrict__ w2) {
    float c = fmaxf(cPtr[0], 0.f);
    float denom = logf(c * MAX_DIST + 1.f);
    for (int idx = threadIdx.x; idx < S_DIM * S_DIM; idx += blockDim.x) {
        int k = idx & 63;
        float r = logf(c * phylo[idx] + 1.f) / denom;
        float b = 0.f;
#pragma unroll
        for (int f = 0; f < 32; ++f) {
            float t = r * w1[f];
            float h = t / (1.f + __expf(-t));
            b += h * w2[f];
        }
        g_bias[idx] = b + am[k];
    }
}

// ---------------- QKV GEMM: A fp32 loaded directly, converted in-kernel ----------------
// C[M,384] = A[M,768] @ W[384,768]^T + bias -> bf16. CTA 128x128, 4 warps 2m x 2n (64x64).
// A: 2-slot double-buffered smem fed by LDG+convert+STS. W: 4-stage cp.async ring.
__global__ void __launch_bounds__(128, 2) gemm_qkv(
    const float* __restrict__ A0, const float* __restrict__ A12,
    const __nv_bfloat16* __restrict__ W0, const float* __restrict__ bias0, __nv_bfloat16* __restrict__ out0,
    const __nv_bfloat16* __restrict__ W1, const float* __restrict__ bias1, __nv_bfloat16* __restrict__ out1,
    const __nv_bfloat16* __restrict__ W2, const float* __restrict__ bias2, __nv_bfloat16* __restrict__ out2)
{
    constexpr int KD = 768;
    constexpr int NBLK = 3;
    constexpr int LDO = AH;
    constexpr int STG = 128 * ROWB;           // 10240
    constexpr int NK = KD / 32;               // 24
    extern __shared__ __align__(16) char smem[];   // 2*STG (A slots) + 4*STG (W ring)

    const int tid = threadIdx.x;
    const int sel = blockIdx.x / NBLK;
    const int n0 = (blockIdx.x % NBLK) * 128;
    const int m0 = blockIdx.y * 128;
    const float* A = (sel == 0) ? A0 : A12;
    const __nv_bfloat16* W = (sel == 0) ? W0 : (sel == 1) ? W1 : W2;
    const float* bias = (sel == 0) ? bias0 : (sel == 1) ? bias1 : bias2;
    __nv_bfloat16* out = (sel == 0) ? out0 : (sel == 1) ? out1 : out2;

    // producers: lc = 8-elem chunk (0..3), lr = base row (0..31), rows lr+32i
    const int lc = tid & 3;
    const int lr = tid >> 2;
    const float* Ag = A + (size_t)(m0 + lr) * KD + lc * 8;
    const __nv_bfloat16* Wg = W + (size_t)(n0 + lr) * KD + lc * 8;
    const unsigned smBase = (unsigned)__cvta_generic_to_shared(smem);
    const unsigned dA = smBase + lr * ROWB + lc * 16;
    const unsigned dW = smBase + 2 * STG + lr * ROWB + lc * 16;

    const int lane = tid & 31, warp = tid >> 5;
    const int wm = (warp & 1) * 64;
    const int wn = (warp >> 1) * 64;
    const unsigned aOff = (unsigned)((wm + (lane & 15)) * ROWB + (lane >> 4) * 16);
    const unsigned bOff = (unsigned)((wn + (lane & 7) + ((lane >> 4) & 1) * 8) * ROWB
                                     + ((lane >> 3) & 1) * 16);

    float acc[4][8][4];
#pragma unroll
    for (int a = 0; a < 4; ++a)
#pragma unroll
        for (int b = 0; b < 8; ++b)
#pragma unroll
            for (int c = 0; c < 4; ++c) acc[a][b][c] = 0.f;

    float4 pre[4][2];

#define LDGA(kt)                                                                  \
    {                                                                             \
        const float* p = Ag + (size_t)(kt) * 32;                                  \
        _Pragma("unroll")                                                         \
        for (int i = 0; i < 4; ++i) {                                             \
            pre[i][0] = *(const float4*)(p + (size_t)i * 32 * KD);                \
            pre[i][1] = *(const float4*)(p + (size_t)i * 32 * KD + 4);            \
        }                                                                         \
    }
#define STSA(slot)                                                                \
    {                                                                             \
        _Pragma("unroll")                                                         \
        for (int i = 0; i < 4; ++i) {                                             \
            unsigned u0 = pack_bf(pre[i][0].x, pre[i][0].y);                      \
            unsigned u1 = pack_bf(pre[i][0].z, pre[i][0].w);                      \
            unsigned u2 = pack_bf(pre[i][1].x, pre[i][1].y);                      \
            unsigned u3 = pack_bf(pre[i][1].z, pre[i][1].w);                      \
            asm volatile("st.shared.v4.b32 [%0], {%1,%2,%3,%4};"                  \
                         :: "r"(dA + (unsigned)(slot) * STG + i * 32 * ROWB),     \
                            "r"(u0), "r"(u1), "r"(u2), "r"(u3));                  \
        }                                                                         \
    }
#define FILLW(slot, kt)                                                           \
    {                                                                             \
        const __nv_bfloat16* p = Wg + (size_t)(kt) * 32;                          \
        _Pragma("unroll")                                                         \
        for (int i = 0; i < 4; ++i)                                               \
            CPA(dW + (unsigned)(slot) * STG + i * 32 * ROWB,                      \
                p + (size_t)i * 32 * KD);                                         \
    }

    // prologue
    LDGA(0);
    FILLW(0, 0); CP_COMMIT();
    FILLW(1, 1); CP_COMMIT();
    FILLW(2, 2); CP_COMMIT();
    STSA(0);

    for (int kt = 0; kt < NK; ++kt) {
        CP_WAIT(2);
        __syncthreads();

        if (kt + 1 < NK) LDGA(kt + 1);
        if (kt + 3 < NK) FILLW((kt + 3) & 3, kt + 3);
        CP_COMMIT();

        const unsigned aBase = smBase + (unsigned)(kt & 1) * STG;
        const unsigned bBase = smBase + 2 * STG + (unsigned)(kt & 3) * STG;

#pragma unroll
        for (int ks = 0; ks < 2; ++ks) {
            unsigned afr[4][4];
#pragma unroll
            for (int mt = 0; mt < 4; ++mt)
                ldm_x4(afr[mt][0], afr[mt][1], afr[mt][2], afr[mt][3],
                       aBase + aOff + mt * 16 * ROWB + ks * 32);
            unsigned bfr[8][2];
#pragma unroll
            for (int np = 0; np < 4; ++np) {
                unsigned b0, b1, b2, b3;
                ldm_x4(b0, b1, b2, b3, bBase + bOff + np * 16 * ROWB + ks * 32);
                bfr[2 * np][0] = b0;     bfr[2 * np][1] = b1;
                bfr[2 * np + 1][0] = b2; bfr[2 * np + 1][1] = b3;
            }
#pragma unroll
            for (int mt = 0; mt < 4; ++mt)
#pragma unroll
                for (int nt = 0; nt < 8; ++nt)
                    mma_bf16(acc[mt][nt], afr[mt], bfr[nt]);
        }

        if (kt + 1 < NK) STSA((kt + 1) & 1);
    }

    // epilogue -> bf16
    const int cRow = lane >> 2;
    const int cCol = (lane & 3) * 2;
#pragma unroll
    for (int mt = 0; mt < 4; ++mt) {
#pragma unroll
        for (int nt = 0; nt < 8; ++nt) {
            const int col = n0 + wn + nt * 8 + cCol;
            const float b0v = bias[col];
            const float b1v = bias[col + 1];
#pragma unroll
            for (int half = 0; half < 2; ++half) {
                const int row = m0 + wm + mt * 16 + cRow + half * 8;
                const float vx = acc[mt][nt][half * 2 + 0] + b0v;
                const float vy = acc[mt][nt][half * 2 + 1] + b1v;
                *(unsigned*)(out + (size_t)row * LDO + col) = pack_bf(vx, vy);
            }
        }
    }
#undef LDGA
#undef STSA
#undef FILLW
}

// ---------------- O GEMM: ctx bf16 @ Wo^T + bias + residual -> fp32 ----------------
__global__ void __launch_bounds__(128, 2) gemm_o(
    const __nv_bfloat16* __restrict__ A,
    const __nv_bfloat16* __restrict__ W, const float* __restrict__ bias,
    float* __restrict__ out, const float* __restrict__ resid)
{
    constexpr int KD = AH;
    constexpr int LDO = H_DIM;
    constexpr int STG = 128 * ROWB;
    constexpr int NSTG = 4;
    constexpr int NK = KD / 32;               // 12
    extern __shared__ __align__(16) char smem[];   // NSTG * 2 * STG

    const int tid = threadIdx.x;
    const int n0 = blockIdx.x * 128;
    const int m0 = blockIdx.y * 128;

    const int lc = tid & 3;
    const int lr = tid >> 2;
    const __nv_bfloat16* Ag = A + (size_t)(m0 + lr) * KD + lc * 8;
    const __nv_bfloat16* Wg = W + (size_t)(n0 + lr) * KD + lc * 8;
    const unsigned smBase = (unsigned)__cvta_generic_to_shared(smem);
    const unsigned dBase = smBase + lr * ROWB + lc * 16;

    const int lane = tid & 31, warp = tid >> 5;
    const int wm = (warp & 1) * 64;
    const int wn = (warp >> 1) * 64;
    const unsigned aOff = (unsigned)((wm + (lane & 15)) * ROWB + (lane >> 4) * 16);
    const unsigned bOff = (unsigned)((wn + (lane & 7) + ((lane >> 4) & 1) * 8) * ROWB
                                     + ((lane >> 3) & 1) * 16);

    float acc[4][8][4];
#pragma unroll
    for (int a = 0; a < 4; ++a)
#pragma unroll
        for (int b = 0; b < 8; ++b)
#pragma unroll
            for (int c = 0; c < 4; ++c) acc[a][b][c] = 0.f;

#define FILL(slot, kt)                                                           \
    {                                                                            \
        const unsigned d = dBase + (unsigned)(slot) * 2 * STG;                   \
        const __nv_bfloat16* ap = Ag + (size_t)(kt) * 32;                        \
        const __nv_bfloat16* wp = Wg + (size_t)(kt) * 32;                        \
        CPA(d, ap);                                                              \
        CPA(d + 32 * ROWB, ap + (size_t)32 * KD);                                \
        CPA(d + 64 * ROWB, ap + (size_t)64 * KD);                                \
        CPA(d + 96 * ROWB, ap + (size_t)96 * KD);                                \
        CPA(d + STG, wp);                                                        \
        CPA(d + STG + 32 * ROWB, wp + (size_t)32 * KD);                          \
        CPA(d + STG + 64 * ROWB, wp + (size_t)64 * KD);                          \
        CPA(d + STG + 96 * ROWB, wp + (size_t)96 * KD);                          \
    }

#pragma unroll
    for (int i = 0; i < NSTG - 1; ++i) {
        FILL(i, i);
        CP_COMMIT();
    }

    for (int kt = 0; kt < NK; ++kt) {
        CP_WAIT(NSTG - 2);
        __syncthreads();

        const int nf = kt + NSTG - 1;
        if (nf < NK) FILL(nf & 3, nf);
        CP_COMMIT();

        const unsigned aBase = smBase + (kt & 3) * 2 * STG;
        const unsigned bBase = aBase + STG;

#pragma unroll
        for (int ks = 0; ks < 2; ++ks) {
            unsigned afr[4][4];
#pragma unroll
            for (int mt = 0; mt < 4; ++mt)
                ldm_x4(afr[mt][0], afr[mt][1], afr[mt][2], afr[mt][3],
                       aBase + aOff + mt * 16 * ROWB + ks * 32);
            unsigned bfr[8][2];
#pragma unroll
            for (int np = 0; np < 4; ++np) {
                unsigned b0, b1, b2, b3;
                ldm_x4(b0, b1, b2, b3, bBase + bOff + np * 16 * ROWB + ks * 32);
                bfr[2 * np][0] = b0;     bfr[2 * np][1] = b1;
                bfr[2 * np + 1][0] = b2; bfr[2 * np + 1][1] = b3;
            }
#pragma unroll
            for (int mt = 0; mt < 4; ++mt)
#pragma unroll
                for (int nt = 0; nt < 8; ++nt)
                    mma_bf16(acc[mt][nt], afr[mt], bfr[nt]);
        }
    }

    const int cRow = lane >> 2;
    const int cCol = (lane & 3) * 2;
#pragma unroll
    for (int mt = 0; mt < 4; ++mt) {
#pragma unroll
        for (int nt = 0; nt < 8; ++nt) {
            const int col = n0 + wn + nt * 8 + cCol;
            const float b0v = bias[col];
            const float b1v = bias[col + 1];
#pragma unroll
            for (int half = 0; half < 2; ++half) {
                const int row = m0 + wm + mt * 16 + cRow + half * 8;
                const float2 r = *(const float2*)(resid + (size_t)row * LDO + col);
                float2 v;
                v.x = acc[mt][nt][half * 2 + 0] + b0v + r.x;
                v.y = acc[mt][nt][half * 2 + 1] + b1v + r.y;
                *(float2*)(out + (size_t)row * LDO + col) = v;
            }
        }
    }
#undef FILL
}

// ---------------- tensor-core attention: one CTA per (l, h), 128 threads ----------------
__global__ void __launch_bounds__(128) attn_kernel() {
    __shared__ __align__(16) __nv_bfloat16 qs[64 * 72];
    __shared__ __align__(16) __nv_bfloat16 ks_[64 * 72];
    __shared__ __align__(16) __nv_bfloat16 vs[64 * 72];
    __shared__ __align__(16) float bs[64 * 68];

    const int l = blockIdx.x, h = blockIdx.y;
    const int tid = threadIdx.x;
    const int lane = tid & 31, w = tid >> 5;
    const size_t base = (size_t)l * 64 * AH + (size_t)h * HD;

    {
        const int r = tid >> 3, c8 = (tid & 7) * 8;
#pragma unroll
        for (int it = 0; it < 4; ++it) {
            const int s = it * 16 + r;
            const size_t g = base + (size_t)s * AH + c8;
            *(uint4*)&qs[s * 72 + c8] = *(const uint4*)(g_qb + g);
            *(uint4*)&ks_[s * 72 + c8] = *(const uint4*)(g_kb + g);
            *(uint4*)&vs[s * 72 + c8] = *(const uint4*)(g_vb + g);
        }
    }
#pragma unroll
    for (int i = 0; i < 8; ++i) {
        const int idx = i * 128 + tid;
        const int r = idx >> 4, c = (idx & 15) * 4;
        *(float4*)&bs[r * 68 + c] = *(const float4*)(g_bias + r * 64 + c);
    }
    __syncthreads();

    const unsigned qB = (unsigned)__cvta_generic_to_shared(qs);
    const unsigned kB = (unsigned)__cvta_generic_to_shared(ks_);
    const unsigned vB = (unsigned)__cvta_generic_to_shared(vs);

    float sc[8][4];
#pragma unroll
    for (int i = 0; i < 8; ++i)
#pragma unroll
        for (int j = 0; j < 4; ++j) sc[i][j] = 0.f;

    const unsigned aAddr = qB + (unsigned)((w * 16 + (lane & 15)) * 144 + (lane >> 4) * 16);
    const unsigned bRow = (lane & 7) + ((lane >> 4) & 1) * 8;
    const unsigned bColB = ((lane >> 3) & 1) * 16;

#pragma unroll
    for (int ksx = 0; ksx < 4; ++ksx) {
        unsigned a[4];
        ldm_x4(a[0], a[1], a[2], a[3], aAddr + ksx * 32);
#pragma unroll
        for (int np = 0; np < 4; ++np) {
            unsigned b[4];
            ldm_x4(b[0], b[1], b[2], b[3],
                   kB + (unsigned)((np * 16 + bRow) * 144) + ksx * 32 + bColB);
            mma_bf16(sc[2 * np], a, b);
            mma_bf16(sc[2 * np + 1], a, b + 2);
        }
    }

    const int rLo = w * 16 + (lane >> 2);
    const int cQ = 2 * (lane & 3);
    float mLo = -1e30f, mHi = -1e30f;
#pragma unroll
    for (int nt = 0; nt < 8; ++nt) {
        const int cb = nt * 8 + cQ;
        sc[nt][0] = sc[nt][0] * 0.125f + bs[rLo * 68 + cb];
        sc[nt][1] = sc[nt][1] * 0.125f + bs[rLo * 68 + cb + 1];
        sc[nt][2] = sc[nt][2] * 0.125f + bs[(rLo + 8) * 68 + cb];
        sc[nt][3] = sc[nt][3] * 0.125f + bs[(rLo + 8) * 68 + cb + 1];
        mLo = fmaxf(mLo, fmaxf(sc[nt][0], sc[nt][1]));
        mHi = fmaxf(mHi, fmaxf(sc[nt][2], sc[nt][3]));
    }
#pragma unroll
    for (int o = 1; o <= 2; o <<= 1) {
        mLo = fmaxf(mLo, __shfl_xor_sync(0xffffffffu, mLo, o));
        mHi = fmaxf(mHi, __shfl_xor_sync(0xffffffffu, mHi, o));
    }
    float sLo = 0.f, sHi = 0.f;
#pragma unroll
    for (int nt = 0; nt < 8; ++nt) {
        sc[nt][0] = __expf(sc[nt][0] - mLo); sLo += sc[nt][0];
        sc[nt][1] = __expf(sc[nt][1] - mLo); sLo += sc[nt][1];
        sc[nt][2] = __expf(sc[nt][2] - mHi); sHi += sc[nt][2];
        sc[nt][3] = __expf(sc[nt][3] - mHi); sHi += sc[nt][3];
    }
#pragma unroll
    for (int o = 1; o <= 2; o <<= 1) {
        sLo += __shfl_xor_sync(0xffffffffu, sLo, o);
        sHi += __shfl_xor_sync(0xffffffffu, sHi, o);
    }
    const float iLo = 1.f / sLo, iHi = 1.f / sHi;
#pragma unroll
    for (int nt = 0; nt < 8; ++nt) {
        sc[nt][0] *= iLo; sc[nt][1] *= iLo;
        sc[nt][2] *= iHi; sc[nt][3] *= iHi;
    }

    float o[8][4];
#pragma unroll
    for (int i = 0; i < 8; ++i)
#pragma unroll
        for (int j = 0; j < 4; ++j) o[i][j] = 0.f;

    const unsigned vRow = (lane & 7) + ((lane >> 3) & 1) * 8;
    const unsigned vColB = ((lane >> 4) & 1) * 16;

#pragma unroll
    for (int kk = 0; kk < 4; ++kk) {
        unsigned ap[4];
        ap[0] = pack_bf(sc[2 * kk][0], sc[2 * kk][1]);
        ap[1] = pack_bf(sc[2 * kk][2], sc[2 * kk][3]);
        ap[2] = pack_bf(sc[2 * kk + 1][0], sc[2 * kk + 1][1]);
        ap[3] = pack_bf(sc[2 * kk + 1][2], sc[2 * kk + 1][3]);
#pragma unroll
        for (int dp = 0; dp < 4; ++dp) {
            unsigned b[4];
            ldm_x4t(b[0], b[1], b[2], b[3],
                    vB + (unsigned)((kk * 16 + vRow) * 144) + dp * 32 + vColB);
            mma_bf16(o[2 * dp], ap, b);
            mma_bf16(o[2 * dp + 1], ap, b + 2);
        }
    }

#pragma unroll
    for (int nt = 0; nt < 8; ++nt) {
        const int col = nt * 8 + cQ;
        *(unsigned*)(g_ctxb + base + (size_t)rLo * AH + col) = pack_bf(o[nt][0], o[nt][1]);
        *(unsigned*)(g_ctxb + base + (size_t)(rLo + 8) * AH + col) = pack_bf(o[nt][2], o[nt][3]);
    }
}

// ---------------- LayerNorm (in place on d_out rows of 768) ----------------
__global__ void __launch_bounds__(256) ln_kernel(float* __restrict__ x,
                                                 const float* __restrict__ g,
                                                 const float* __restrict__ b) {
    const size_t row = blockIdx.x;
    float* p = x + row * H_DIM;
    const int tid = threadIdx.x;

    float v0 = p[tid], v1 = p[tid + 256], v2 = p[tid + 512];
    float s = v0 + v1 + v2;
    float q = v0 * v0 + v1 * v1 + v2 * v2;
#pragma unroll
    for (int o = 16; o; o >>= 1) {
        s += __shfl_xor_sync(0xffffffffu, s, o);
        q += __shfl_xor_sync(0xffffffffu, q, o);
    }
    __shared__ float ss[8], qs[8];
    __shared__ float mu_s, rs_s;
    if ((tid & 31) == 0) { ss[tid >> 5] = s; qs[tid >> 5] = q; }
    __syncthreads();
    if (tid == 0) {
        float S = 0.f, Q = 0.f;
#pragma unroll
        for (int i = 0; i < 8; ++i) { S += ss[i]; Q += qs[i]; }
        const float mu = S * (1.f / 768.f);
        const float var = Q * (1.f / 768.f) - mu * mu;
        mu_s = mu;
        rs_s = rsqrtf(var + 1e-12f);
    }
    __syncthreads();
    const float mu = mu_s, rs = rs_s;
    p[tid]       = (v0 - mu) * rs * g[tid]       + b[tid];
    p[tid + 256] = (v1 - mu) * rs * g[tid + 256] + b[tid + 256];
    p[tid + 512] = (v2 - mu) * rs * g[tid + 512] + b[tid + 512];
}

// ---------------- launch ----------------
extern "C" void kernel_launch(void* const* d_in, const int* in_sizes, int n_in,
                              void* d_out, int out_size) {
    const float* hidden = (const float*)d_in[0];
    const float* source = (const float*)d_in[1];
    const float* amask  = (const float*)d_in[2];
    const float* phylo  = (const float*)d_in[3];
    const float* cP     = (const float*)d_in[4];
    const float* w1     = (const float*)d_in[5];
    const float* w2     = (const float*)d_in[6];
    const float* Wq     = (const float*)d_in[7];
    const float* bq     = (const float*)d_in[8];
    const float* Wk     = (const float*)d_in[9];
    const float* bk     = (const float*)d_in[10];
    const float* Wv     = (const float*)d_in[11];
    const float* bv     = (const float*)d_in[12];
    const float* Wo     = (const float*)d_in[13];
    const float* bo     = (const float*)d_in[14];
    const float* lng    = (const float*)d_in[15];
    const float* lnb    = (const float*)d_in[16];
    float* out = (float*)d_out;

    void *cb, *qa, *ka, *va, *wqb, *wkb, *wvb, *wob;
    cudaGetSymbolAddress(&cb, g_ctxb);
    cudaGetSymbolAddress(&qa, g_qb);
    cudaGetSymbolAddress(&ka, g_kb);
    cudaGetSymbolAddress(&va, g_vb);
    cudaGetSymbolAddress(&wqb, g_Wqb);
    cudaGetSymbolAddress(&wkb, g_Wkb);
    cudaGetSymbolAddress(&wvb, g_Wvb);
    cudaGetSymbolAddress(&wob, g_Wob);

    const int SMEM_QKV = 6 * 128 * ROWB;    // 61440: 2 A slots + 4 W stages
    const int SMEM_O   = 8 * 128 * ROWB;    // 81920: 4 stages x (A|W)
    cudaFuncSetAttribute(gemm_qkv, cudaFuncAttributeMaxDynamicSharedMemorySize, SMEM_QKV);
    cudaFuncSetAttribute(gemm_o,   cudaFuncAttributeMaxDynamicSharedMemorySize, SMEM_O);

    cvt_w<<<dim3(288, 4), 256>>>((const float4*)Wq, (const float4*)Wk,
                                 (const float4*)Wv, (const float4*)Wo);
    bias_kernel<<<1, 256>>>(phylo, amask, cP, w1, w2);

    // fused Q + K + V projections; A read as fp32 directly (sel 0: hidden, 1/2: source)
    gemm_qkv<<<dim3(9, 512), 128, SMEM_QKV>>>(
        hidden, source,
        (const __nv_bfloat16*)wqb, bq, (__nv_bfloat16*)qa,
        (const __nv_bfloat16*)wkb, bk, (__nv_bfloat16*)ka,
        (const __nv_bfloat16*)wvb, bv, (__nv_bfloat16*)va);

    attn_kernel<<<dim3(L_DIM, NH), 128>>>();

    // Output projection + bias + residual -> fp32
    gemm_o<<<dim3(6, 512), 128, SMEM_O>>>(
        (const __nv_bfloat16*)cb, (const __nv_bfloat16*)wob, bo, out, hidden);

    ln_kernel<<<M_TOK, 256>>>(out, lng, lnb);
}

// round 17
// speedup vs baseline: 1.2710x; 1.0373x over previous
#include <cuda_runtime.h>
#include <cuda_bf16.h>
#include <math.h>
#include <stdint.h>

#define L_DIM   1024
#define S_DIM   64
#define H_DIM   768
#define AH      384
#define NH      6
#define HD      64
#define M_TOK   65536
#define MAX_DIST 20.0f
#define ROWB    80          // padded smem row bytes (32 bf16 + 16B pad) -> conflict-free ldmatrix

// ---------------- scratch (device globals; no allocs allowed) ----------------
__device__ __align__(16) __nv_bfloat16 g_qb[M_TOK * AH];
__device__ __align__(16) __nv_bfloat16 g_kb[M_TOK * AH];
__device__ __align__(16) __nv_bfloat16 g_vb[M_TOK * AH];
__device__ __align__(16) __nv_bfloat16 g_ctxb[M_TOK * AH];
__device__ __align__(16) __nv_bfloat16 g_Wqb[AH * H_DIM];
__device__ __align__(16) __nv_bfloat16 g_Wkb[AH * H_DIM];
__device__ __align__(16) __nv_bfloat16 g_Wvb[AH * H_DIM];
__device__ __align__(16) __nv_bfloat16 g_Wob[H_DIM * AH];
__device__ __align__(16) float g_bias[S_DIM * S_DIM];

// ---------------- asm helpers ----------------
#define CPA(dst, src) asm volatile("cp.async.cg.shared.global [%0], [%1], 16;" :: "r"(dst), "l"(src))
#define CP_COMMIT()   asm volatile("cp.async.commit_group;")
#define CP_WAIT(n)    asm volatile("cp.async.wait_group %0;" :: "n"(n))

__device__ __forceinline__ void ldm_x4(unsigned& r0, unsigned& r1, unsigned& r2, unsigned& r3,
                                       unsigned addr) {
    asm volatile("ldmatrix.sync.aligned.m8n8.x4.shared.b16 {%0,%1,%2,%3}, [%4];"
                 : "=r"(r0), "=r"(r1), "=r"(r2), "=r"(r3) : "r"(addr));
}
__device__ __forceinline__ void ldm_x4t(unsigned& r0, unsigned& r1, unsigned& r2, unsigned& r3,
                                        unsigned addr) {
    asm volatile("ldmatrix.sync.aligned.m8n8.x4.trans.shared.b16 {%0,%1,%2,%3}, [%4];"
                 : "=r"(r0), "=r"(r1), "=r"(r2), "=r"(r3) : "r"(addr));
}

__device__ __forceinline__ void mma_bf16(float* c, const unsigned* a, const unsigned* b) {
    asm volatile(
        "mma.sync.aligned.m16n8k16.row.col.f32.bf16.bf16.f32 "
        "{%0,%1,%2,%3},{%4,%5,%6,%7},{%8,%9},{%0,%1,%2,%3};"
        : "+f"(c[0]), "+f"(c[1]), "+f"(c[2]), "+f"(c[3])
        : "r"(a[0]), "r"(a[1]), "r"(a[2]), "r"(a[3]), "r"(b[0]), "r"(b[1]));
}

__device__ __forceinline__ unsigned pack_bf(float a, float b) {
    __nv_bfloat162 t = __floats2bfloat162_rn(a, b);
    return *reinterpret_cast<unsigned*>(&t);
}

// ---------------- weights fp32 -> bf16 ----------------
__global__ void __launch_bounds__(256) cvt_w(const float4* __restrict__ wq,
                                             const float4* __restrict__ wk,
                                             const float4* __restrict__ wv,
                                             const float4* __restrict__ wo) {
    const int per = AH * H_DIM / 4;
    const int a = blockIdx.y;
    const float4* src = (a == 0) ? wq : (a == 1) ? wk : (a == 2) ? wv : wo;
    uint2* dst = (a == 0) ? (uint2*)g_Wqb : (a == 1) ? (uint2*)g_Wkb
               : (a == 2) ? (uint2*)g_Wvb : (uint2*)g_Wob;
    for (int i = blockIdx.x * blockDim.x + threadIdx.x; i < per; i += gridDim.x * blockDim.x) {
        float4 v = src[i];
        dst[i] = make_uint2(pack_bf(v.x, v.y), pack_bf(v.z, v.w));
    }
}

// ---------------- FIRE bias + attention mask ----------------
__global__ void bias_kernel(const float* __restrict__ phylo, const float* __restrict__ am,
                            const float* __restrict__ cPtr, const float* __restrict__ w1,
                            const float* __restrict__ w2) {
    float c = fmaxf(cPtr[0], 0.f);
    float denom = logf(c * MAX_DIST + 1.f);
    for (int idx = threadIdx.x; idx < S_DIM * S_DIM; idx += blockDim.x) {
        int k = idx & 63;
        float r = logf(c * phylo[idx] + 1.f) / denom;
        float b = 0.f;
#pragma unroll
        for (int f = 0; f < 32; ++f) {
            float t = r * w1[f];
            float h = t / (1.f + __expf(-t));
            b += h * w2[f];
        }
        g_bias[idx] = b + am[k];
    }
}

// ---------------- QKV GEMM: A fp32 loaded directly, converted in-kernel ----------------
// C[M,384] = A[M,768] @ W[384,768]^T + bias -> bf16. CTA 128x128, 4 warps 2m x 2n (64x64).
// A: 2-slot double-buffered smem fed by LDG+convert+STS. W: 4-stage cp.async ring.
__global__ void __launch_bounds__(128, 2) gemm_qkv(
    const float* __restrict__ A0, const float* __restrict__ A12,
    const __nv_bfloat16* __restrict__ W0, const float* __restrict__ bias0, __nv_bfloat16* __restrict__ out0,
    const __nv_bfloat16* __restrict__ W1, const float* __restrict__ bias1, __nv_bfloat16* __restrict__ out1,
    const __nv_bfloat16* __restrict__ W2, const float* __restrict__ bias2, __nv_bfloat16* __restrict__ out2)
{
    constexpr int KD = 768;
    constexpr int NBLK = 3;
    constexpr int LDO = AH;
    constexpr int STG = 128 * ROWB;           // 10240
    constexpr int NK = KD / 32;               // 24
    extern __shared__ __align__(16) char smem[];   // 2*STG (A slots) + 4*STG (W ring)

    const int tid = threadIdx.x;
    const int sel = blockIdx.x / NBLK;
    const int n0 = (blockIdx.x % NBLK) * 128;
    const int m0 = blockIdx.y * 128;
    const float* A = (sel == 0) ? A0 : A12;
    const __nv_bfloat16* W = (sel == 0) ? W0 : (sel == 1) ? W1 : W2;
    const float* bias = (sel == 0) ? bias0 : (sel == 1) ? bias1 : bias2;
    __nv_bfloat16* out = (sel == 0) ? out0 : (sel == 1) ? out1 : out2;

    // producers: lc = 8-elem chunk (0..3), lr = base row (0..31), rows lr+32i
    const int lc = tid & 3;
    const int lr = tid >> 2;
    const float* Ag = A + (size_t)(m0 + lr) * KD + lc * 8;
    const __nv_bfloat16* Wg = W + (size_t)(n0 + lr) * KD + lc * 8;
    const unsigned smBase = (unsigned)__cvta_generic_to_shared(smem);
    const unsigned dA = smBase + lr * ROWB + lc * 16;
    const unsigned dW = smBase + 2 * STG + lr * ROWB + lc * 16;

    const int lane = tid & 31, warp = tid >> 5;
    const int wm = (warp & 1) * 64;
    const int wn = (warp >> 1) * 64;
    const unsigned aOff = (unsigned)((wm + (lane & 15)) * ROWB + (lane >> 4) * 16);
    const unsigned bOff = (unsigned)((wn + (lane & 7) + ((lane >> 4) & 1) * 8) * ROWB
                                     + ((lane >> 3) & 1) * 16);

    float acc[4][8][4];
#pragma unroll
    for (int a = 0; a < 4; ++a)
#pragma unroll
        for (int b = 0; b < 8; ++b)
#pragma unroll
            for (int c = 0; c < 4; ++c) acc[a][b][c] = 0.f;

    float4 pre[4][2];

#define LDGA(kt)                                                                  \
    {                                                                             \
        const float* p = Ag + (size_t)(kt) * 32;                                  \
        _Pragma("unroll")                                                         \
        for (int i = 0; i < 4; ++i) {                                             \
            pre[i][0] = *(const float4*)(p + (size_t)i * 32 * KD);                \
            pre[i][1] = *(const float4*)(p + (size_t)i * 32 * KD + 4);            \
        }                                                                         \
    }
#define STSA(slot)                                                                \
    {                                                                             \
        _Pragma("unroll")                                                         \
        for (int i = 0; i < 4; ++i) {                                             \
            unsigned u0 = pack_bf(pre[i][0].x, pre[i][0].y);                      \
            unsigned u1 = pack_bf(pre[i][0].z, pre[i][0].w);                      \
            unsigned u2 = pack_bf(pre[i][1].x, pre[i][1].y);                      \
            unsigned u3 = pack_bf(pre[i][1].z, pre[i][1].w);                      \
            asm volatile("st.shared.v4.b32 [%0], {%1,%2,%3,%4};"                  \
                         :: "r"(dA + (unsigned)(slot) * STG + i * 32 * ROWB),     \
                            "r"(u0), "r"(u1), "r"(u2), "r"(u3));                  \
        }                                                                         \
    }
#define FILLW(slot, kt)                                                           \
    {                                                                             \
        const __nv_bfloat16* p = Wg + (size_t)(kt) * 32;                          \
        _Pragma("unroll")                                                         \
        for (int i = 0; i < 4; ++i)                                               \
            CPA(dW + (unsigned)(slot) * STG + i * 32 * ROWB,                      \
                p + (size_t)i * 32 * KD);                                         \
    }

    // prologue
    LDGA(0);
    FILLW(0, 0); CP_COMMIT();
    FILLW(1, 1); CP_COMMIT();
    FILLW(2, 2); CP_COMMIT();
    STSA(0);

    for (int kt = 0; kt < NK; ++kt) {
        CP_WAIT(2);
        __syncthreads();

        if (kt + 1 < NK) LDGA(kt + 1);
        if (kt + 3 < NK) FILLW((kt + 3) & 3, kt + 3);
        CP_COMMIT();

        const unsigned aBase = smBase + (unsigned)(kt & 1) * STG;
        const unsigned bBase = smBase + 2 * STG + (unsigned)(kt & 3) * STG;

#pragma unroll
        for (int ks = 0; ks < 2; ++ks) {
            unsigned afr[4][4];
#pragma unroll
            for (int mt = 0; mt < 4; ++mt)
                ldm_x4(afr[mt][0], afr[mt][1], afr[mt][2], afr[mt][3],
                       aBase + aOff + mt * 16 * ROWB + ks * 32);
            unsigned bfr[8][2];
#pragma unroll
            for (int np = 0; np < 4; ++np) {
                unsigned b0, b1, b2, b3;
                ldm_x4(b0, b1, b2, b3, bBase + bOff + np * 16 * ROWB + ks * 32);
                bfr[2 * np][0] = b0;     bfr[2 * np][1] = b1;
                bfr[2 * np + 1][0] = b2; bfr[2 * np + 1][1] = b3;
            }
#pragma unroll
            for (int mt = 0; mt < 4; ++mt)
#pragma unroll
                for (int nt = 0; nt < 8; ++nt)
                    mma_bf16(acc[mt][nt], afr[mt], bfr[nt]);
        }

        if (kt + 1 < NK) STSA((kt + 1) & 1);
    }

    // epilogue -> bf16
    const int cRow = lane >> 2;
    const int cCol = (lane & 3) * 2;
#pragma unroll
    for (int mt = 0; mt < 4; ++mt) {
#pragma unroll
        for (int nt = 0; nt < 8; ++nt) {
            const int col = n0 + wn + nt * 8 + cCol;
            const float b0v = bias[col];
            const float b1v = bias[col + 1];
#pragma unroll
            for (int half = 0; half < 2; ++half) {
                const int row = m0 + wm + mt * 16 + cRow + half * 8;
                const float vx = acc[mt][nt][half * 2 + 0] + b0v;
                const float vy = acc[mt][nt][half * 2 + 1] + b1v;
                *(unsigned*)(out + (size_t)row * LDO + col) = pack_bf(vx, vy);
            }
        }
    }
#undef LDGA
#undef STSA
#undef FILLW
}

// ---------------- O GEMM: ctx bf16 @ Wo^T + bias + residual -> fp32 ----------------
__global__ void __launch_bounds__(128, 2) gemm_o(
    const __nv_bfloat16* __restrict__ A,
    const __nv_bfloat16* __restrict__ W, const float* __restrict__ bias,
    float* __restrict__ out, const float* __restrict__ resid)
{
    constexpr int KD = AH;
    constexpr int LDO = H_DIM;
    constexpr int STG = 128 * ROWB;
    constexpr int NSTG = 4;
    constexpr int NK = KD / 32;               // 12
    extern __shared__ __align__(16) char smem[];   // NSTG * 2 * STG

    const int tid = threadIdx.x;
    const int n0 = blockIdx.x * 128;
    const int m0 = blockIdx.y * 128;

    const int lc = tid & 3;
    const int lr = tid >> 2;
    const __nv_bfloat16* Ag = A + (size_t)(m0 + lr) * KD + lc * 8;
    const __nv_bfloat16* Wg = W + (size_t)(n0 + lr) * KD + lc * 8;
    const unsigned smBase = (unsigned)__cvta_generic_to_shared(smem);
    const unsigned dBase = smBase + lr * ROWB + lc * 16;

    const int lane = tid & 31, warp = tid >> 5;
    const int wm = (warp & 1) * 64;
    const int wn = (warp >> 1) * 64;
    const unsigned aOff = (unsigned)((wm + (lane & 15)) * ROWB + (lane >> 4) * 16);
    const unsigned bOff = (unsigned)((wn + (lane & 7) + ((lane >> 4) & 1) * 8) * ROWB
                                     + ((lane >> 3) & 1) * 16);

    float acc[4][8][4];
#pragma unroll
    for (int a = 0; a < 4; ++a)
#pragma unroll
        for (int b = 0; b < 8; ++b)
#pragma unroll
            for (int c = 0; c < 4; ++c) acc[a][b][c] = 0.f;

#define FILL(slot, kt)                                                           \
    {                                                                            \
        const unsigned d = dBase + (unsigned)(slot) * 2 * STG;                   \
        const __nv_bfloat16* ap = Ag + (size_t)(kt) * 32;                        \
        const __nv_bfloat16* wp = Wg + (size_t)(kt) * 32;                        \
        CPA(d, ap);                                                              \
        CPA(d + 32 * ROWB, ap + (size_t)32 * KD);                                \
        CPA(d + 64 * ROWB, ap + (size_t)64 * KD);                                \
        CPA(d + 96 * ROWB, ap + (size_t)96 * KD);                                \
        CPA(d + STG, wp);                                                        \
        CPA(d + STG + 32 * ROWB, wp + (size_t)32 * KD);                          \
        CPA(d + STG + 64 * ROWB, wp + (size_t)64 * KD);                          \
        CPA(d + STG + 96 * ROWB, wp + (size_t)96 * KD);                          \
    }

#pragma unroll
    for (int i = 0; i < NSTG - 1; ++i) {
        FILL(i, i);
        CP_COMMIT();
    }

    for (int kt = 0; kt < NK; ++kt) {
        CP_WAIT(NSTG - 2);
        __syncthreads();

        const int nf = kt + NSTG - 1;
        if (nf < NK) FILL(nf & 3, nf);
        CP_COMMIT();

        const unsigned aBase = smBase + (kt & 3) * 2 * STG;
        const unsigned bBase = aBase + STG;

#pragma unroll
        for (int ks = 0; ks < 2; ++ks) {
            unsigned afr[4][4];
#pragma unroll
            for (int mt = 0; mt < 4; ++mt)
                ldm_x4(afr[mt][0], afr[mt][1], afr[mt][2], afr[mt][3],
                       aBase + aOff + mt * 16 * ROWB + ks * 32);
            unsigned bfr[8][2];
#pragma unroll
            for (int np = 0; np < 4; ++np) {
                unsigned b0, b1, b2, b3;
                ldm_x4(b0, b1, b2, b3, bBase + bOff + np * 16 * ROWB + ks * 32);
                bfr[2 * np][0] = b0;     bfr[2 * np][1] = b1;
                bfr[2 * np + 1][0] = b2; bfr[2 * np + 1][1] = b3;
            }
#pragma unroll
            for (int mt = 0; mt < 4; ++mt)
#pragma unroll
                for (int nt = 0; nt < 8; ++nt)
                    mma_bf16(acc[mt][nt], afr[mt], bfr[nt]);
        }
    }

    const int cRow = lane >> 2;
    const int cCol = (lane & 3) * 2;
#pragma unroll
    for (int mt = 0; mt < 4; ++mt) {
#pragma unroll
        for (int nt = 0; nt < 8; ++nt) {
            const int col = n0 + wn + nt * 8 + cCol;
            const float b0v = bias[col];
            const float b1v = bias[col + 1];
#pragma unroll
            for (int half = 0; half < 2; ++half) {
                const int row = m0 + wm + mt * 16 + cRow + half * 8;
                const float2 r = *(const float2*)(resid + (size_t)row * LDO + col);
                float2 v;
                v.x = acc[mt][nt][half * 2 + 0] + b0v + r.x;
                v.y = acc[mt][nt][half * 2 + 1] + b1v + r.y;
                *(float2*)(out + (size_t)row * LDO + col) = v;
            }
        }
    }
#undef FILL
}

// ---------------- tensor-core attention: one CTA per (l, h), 128 threads ----------------
// bias read directly from g_bias (L2-hot 16KB) -- no smem staging.
__global__ void __launch_bounds__(128) attn_kernel() {
    __shared__ __align__(16) __nv_bfloat16 qs[64 * 72];
    __shared__ __align__(16) __nv_bfloat16 ks_[64 * 72];
    __shared__ __align__(16) __nv_bfloat16 vs[64 * 72];

    const int l = blockIdx.x, h = blockIdx.y;
    const int tid = threadIdx.x;
    const int lane = tid & 31, w = tid >> 5;
    const size_t base = (size_t)l * 64 * AH + (size_t)h * HD;

    {
        const int r = tid >> 3, c8 = (tid & 7) * 8;
#pragma unroll
        for (int it = 0; it < 4; ++it) {
            const int s = it * 16 + r;
            const size_t g = base + (size_t)s * AH + c8;
            *(uint4*)&qs[s * 72 + c8] = *(const uint4*)(g_qb + g);
            *(uint4*)&ks_[s * 72 + c8] = *(const uint4*)(g_kb + g);
            *(uint4*)&vs[s * 72 + c8] = *(const uint4*)(g_vb + g);
        }
    }
    __syncthreads();

    const unsigned qB = (unsigned)__cvta_generic_to_shared(qs);
    const unsigned kB = (unsigned)__cvta_generic_to_shared(ks_);
    const unsigned vB = (unsigned)__cvta_generic_to_shared(vs);

    float sc[8][4];
#pragma unroll
    for (int i = 0; i < 8; ++i)
#pragma unroll
        for (int j = 0; j < 4; ++j) sc[i][j] = 0.f;

    const unsigned aAddr = qB + (unsigned)((w * 16 + (lane & 15)) * 144 + (lane >> 4) * 16);
    const unsigned bRow = (lane & 7) + ((lane >> 4) & 1) * 8;
    const unsigned bColB = ((lane >> 3) & 1) * 16;

#pragma unroll
    for (int ksx = 0; ksx < 4; ++ksx) {
        unsigned a[4];
        ldm_x4(a[0], a[1], a[2], a[3], aAddr + ksx * 32);
#pragma unroll
        for (int np = 0; np < 4; ++np) {
            unsigned b[4];
            ldm_x4(b[0], b[1], b[2], b[3],
                   kB + (unsigned)((np * 16 + bRow) * 144) + ksx * 32 + bColB);
            mma_bf16(sc[2 * np], a, b);
            mma_bf16(sc[2 * np + 1], a, b + 2);
        }
    }

    const int rLo = w * 16 + (lane >> 2);
    const int cQ = 2 * (lane & 3);
    const float* bLo = g_bias + rLo * 64 + cQ;
    const float* bHi = g_bias + (rLo + 8) * 64 + cQ;
    float mLo = -1e30f, mHi = -1e30f;
#pragma unroll
    for (int nt = 0; nt < 8; ++nt) {
        const float2 bl = __ldg((const float2*)(bLo + nt * 8));
        const float2 bh = __ldg((const float2*)(bHi + nt * 8));
        sc[nt][0] = sc[nt][0] * 0.125f + bl.x;
        sc[nt][1] = sc[nt][1] * 0.125f + bl.y;
        sc[nt][2] = sc[nt][2] * 0.125f + bh.x;
        sc[nt][3] = sc[nt][3] * 0.125f + bh.y;
        mLo = fmaxf(mLo, fmaxf(sc[nt][0], sc[nt][1]));
        mHi = fmaxf(mHi, fmaxf(sc[nt][2], sc[nt][3]));
    }
#pragma unroll
    for (int o = 1; o <= 2; o <<= 1) {
        mLo = fmaxf(mLo, __shfl_xor_sync(0xffffffffu, mLo, o));
        mHi = fmaxf(mHi, __shfl_xor_sync(0xffffffffu, mHi, o));
    }
    float sLo = 0.f, sHi = 0.f;
#pragma unroll
    for (int nt = 0; nt < 8; ++nt) {
        sc[nt][0] = __expf(sc[nt][0] - mLo); sLo += sc[nt][0];
        sc[nt][1] = __expf(sc[nt][1] - mLo); sLo += sc[nt][1];
        sc[nt][2] = __expf(sc[nt][2] - mHi); sHi += sc[nt][2];
        sc[nt][3] = __expf(sc[nt][3] - mHi); sHi += sc[nt][3];
    }
#pragma unroll
    for (int o = 1; o <= 2; o <<= 1) {
        sLo += __shfl_xor_sync(0xffffffffu, sLo, o);
        sHi += __shfl_xor_sync(0xffffffffu, sHi, o);
    }
    const float iLo = 1.f / sLo, iHi = 1.f / sHi;
#pragma unroll
    for (int nt = 0; nt < 8; ++nt) {
        sc[nt][0] *= iLo; sc[nt][1] *= iLo;
        sc[nt][2] *= iHi; sc[nt][3] *= iHi;
    }

    float o[8][4];
#pragma unroll
    for (int i = 0; i < 8; ++i)
#pragma unroll
        for (int j = 0; j < 4; ++j) o[i][j] = 0.f;

    const unsigned vRow = (lane & 7) + ((lane >> 3) & 1) * 8;
    const unsigned vColB = ((lane >> 4) & 1) * 16;

#pragma unroll
    for (int kk = 0; kk < 4; ++kk) {
        unsigned ap[4];
        ap[0] = pack_bf(sc[2 * kk][0], sc[2 * kk][1]);
        ap[1] = pack_bf(sc[2 * kk][2], sc[2 * kk][3]);
        ap[2] = pack_bf(sc[2 * kk + 1][0], sc[2 * kk + 1][1]);
        ap[3] = pack_bf(sc[2 * kk + 1][2], sc[2 * kk + 1][3]);
#pragma unroll
        for (int dp = 0; dp < 4; ++dp) {
            unsigned b[4];
            ldm_x4t(b[0], b[1], b[2], b[3],
                    vB + (unsigned)((kk * 16 + vRow) * 144) + dp * 32 + vColB);
            mma_bf16(o[2 * dp], ap, b);
            mma_bf16(o[2 * dp + 1], ap, b + 2);
        }
    }

#pragma unroll
    for (int nt = 0; nt < 8; ++nt) {
        const int col = nt * 8 + cQ;
        *(unsigned*)(g_ctxb + base + (size_t)rLo * AH + col) = pack_bf(o[nt][0], o[nt][1]);
        *(unsigned*)(g_ctxb + base + (size_t)(rLo + 8) * AH + col) = pack_bf(o[nt][2], o[nt][3]);
    }
}

// ---------------- LayerNorm (in place, vectorized: 4 rows per 256-thread CTA) ----------
__global__ void __launch_bounds__(256) ln_kernel(float* __restrict__ x,
                                                 const float* __restrict__ g,
                                                 const float* __restrict__ b) {
    const int tid = threadIdx.x;
    const int rsub = tid >> 6;            // 0..3 : row within block
    const int t = tid & 63;               // 0..63 : thread within row
    const size_t row = (size_t)blockIdx.x * 4 + rsub;
    float* p = x + row * H_DIM;

    float4 v[3];
#pragma unroll
    for (int k = 0; k < 3; ++k) v[k] = *(const float4*)(p + (t + k * 64) * 4);

    float s = 0.f, q = 0.f;
#pragma unroll
    for (int k = 0; k < 3; ++k) {
        s += v[k].x + v[k].y + v[k].z + v[k].w;
        q += v[k].x * v[k].x + v[k].y * v[k].y + v[k].z * v[k].z + v[k].w * v[k].w;
    }
#pragma unroll
    for (int o = 16; o; o >>= 1) {
        s += __shfl_xor_sync(0xffffffffu, s, o);
        q += __shfl_xor_sync(0xffffffffu, q, o);
    }
    // combine the 2 warps of each row via smem
    __shared__ float ss[4][2], qs[4][2];
    __shared__ float mu_s[4], rs_s[4];
    const int wsub = (t >> 5);            // warp within row: 0/1
    if ((t & 31) == 0) { ss[rsub][wsub] = s; qs[rsub][wsub] = q; }
    __syncthreads();
    if (t == 0) {
        const float S = ss[rsub][0] + ss[rsub][1];
        const float Q = qs[rsub][0] + qs[rsub][1];
        const float mu = S * (1.f / 768.f);
        const float var = Q * (1.f / 768.f) - mu * mu;
        mu_s[rsub] = mu;
        rs_s[rsub] = rsqrtf(var + 1e-12f);
    }
    __syncthreads();
    const float mu = mu_s[rsub], rs = rs_s[rsub];
#pragma unroll
    for (int k = 0; k < 3; ++k) {
        const int c = (t + k * 64) * 4;
        const float4 gv = *(const float4*)(g + c);
        const float4 bv = *(const float4*)(b + c);
        float4 o;
        o.x = (v[k].x - mu) * rs * gv.x + bv.x;
        o.y = (v[k].y - mu) * rs * gv.y + bv.y;
        o.z = (v[k].z - mu) * rs * gv.z + bv.z;
        o.w = (v[k].w - mu) * rs * gv.w + bv.w;
        *(float4*)(p + c) = o;
    }
}

// ---------------- launch ----------------
extern "C" void kernel_launch(void* const* d_in, const int* in_sizes, int n_in,
                              void* d_out, int out_size) {
    const float* hidden = (const float*)d_in[0];
    const float* source = (const float*)d_in[1];
    const float* amask  = (const float*)d_in[2];
    const float* phylo  = (const float*)d_in[3];
    const float* cP     = (const float*)d_in[4];
    const float* w1     = (const float*)d_in[5];
    const float* w2     = (const float*)d_in[6];
    const float* Wq     = (const float*)d_in[7];
    const float* bq     = (const float*)d_in[8];
    const float* Wk     = (const float*)d_in[9];
    const float* bk     = (const float*)d_in[10];
    const float* Wv     = (const float*)d_in[11];
    const float* bv     = (const float*)d_in[12];
    const float* Wo     = (const float*)d_in[13];
    const float* bo     = (const float*)d_in[14];
    const float* lng    = (const float*)d_in[15];
    const float* lnb    = (const float*)d_in[16];
    float* out = (float*)d_out;

    void *cb, *qa, *ka, *va, *wqb, *wkb, *wvb, *wob;
    cudaGetSymbolAddress(&cb, g_ctxb);
    cudaGetSymbolAddress(&qa, g_qb);
    cudaGetSymbolAddress(&ka, g_kb);
    cudaGetSymbolAddress(&va, g_vb);
    cudaGetSymbolAddress(&wqb, g_Wqb);
    cudaGetSymbolAddress(&wkb, g_Wkb);
    cudaGetSymbolAddress(&wvb, g_Wvb);
    cudaGetSymbolAddress(&wob, g_Wob);

    const int SMEM_QKV = 6 * 128 * ROWB;    // 61440: 2 A slots + 4 W stages
    const int SMEM_O   = 8 * 128 * ROWB;    // 81920: 4 stages x (A|W)
    cudaFuncSetAttribute(gemm_qkv, cudaFuncAttributeMaxDynamicSharedMemorySize, SMEM_QKV);
    cudaFuncSetAttribute(gemm_o,   cudaFuncAttributeMaxDynamicSharedMemorySize, SMEM_O);

    cvt_w<<<dim3(288, 4), 256>>>((const float4*)Wq, (const float4*)Wk,
                                 (const float4*)Wv, (const float4*)Wo);
    bias_kernel<<<1, 256>>>(phylo, amask, cP, w1, w2);

    // fused Q + K + V projections; A read as fp32 directly (sel 0: hidden, 1/2: source)
    gemm_qkv<<<dim3(9, 512), 128, SMEM_QKV>>>(
        hidden, source,
        (const __nv_bfloat16*)wqb, bq, (__nv_bfloat16*)qa,
        (const __nv_bfloat16*)wkb, bk, (__nv_bfloat16*)ka,
        (const __nv_bfloat16*)wvb, bv, (__nv_bfloat16*)va);

    attn_kernel<<<dim3(L_DIM, NH), 128>>>();

    // Output projection + bias + residual -> fp32
    gemm_o<<<dim3(6, 512), 128, SMEM_O>>>(
        (const __nv_bfloat16*)cb, (const __nv_bfloat16*)wob, bo, out, hidden);

    ln_kernel<<<M_TOK / 4, 256>>>(out, lng, lnb);
}